// round 7
// baseline (speedup 1.0000x reference)
#include <cuda_runtime.h>
#include <cuda_bf16.h>
#include <math.h>
#include <stdint.h>

// Problem constants
#define Bc   2
#define Sc   2048
#define Dc   1024
#define Hc   16
#define HDc  64
#define Mtot 4096
#define SCALE 0.03125f          // 1/sqrt(1024)
#define NEGINF (-1e30f)

typedef unsigned long long u64;
typedef uint32_t u32;

// ---------------- scratch (device globals; referenced ONLY in device code) --
__device__ __nv_bfloat16 g_qh[(size_t)Bc * Hc * Sc * HDc];   // [bh, s, hd], pre-scaled
__device__ __nv_bfloat16 g_ql[(size_t)Bc * Hc * Sc * HDc];
__device__ __nv_bfloat16 g_kh[(size_t)Bc * Hc * Sc * HDc];
__device__ __nv_bfloat16 g_kl[(size_t)Bc * Hc * Sc * HDc];
__device__ __nv_bfloat16 g_vh[(size_t)Bc * Hc * Sc * HDc];
__device__ __nv_bfloat16 g_vl[(size_t)Bc * Hc * Sc * HDc];

__device__ __nv_bfloat16 g_ah[(size_t)Mtot * Dc];      // A hi (X, then attn out)
__device__ __nv_bfloat16 g_al[(size_t)Mtot * Dc];
__device__ __nv_bfloat16 g_wqh[(size_t)3 * Dc * Dc];   // W_qkv^T hi  [3072, 1024]
__device__ __nv_bfloat16 g_wql[(size_t)3 * Dc * Dc];
__device__ __nv_bfloat16 g_woh[(size_t)Dc * Dc];       // W_out^T hi  [1024, 1024]
__device__ __nv_bfloat16 g_wol[(size_t)Dc * Dc];

// ---------------- PTX helpers (non-arch-specific, sm_80 class) --------------
__device__ __forceinline__ u32 smem_u32_of(const void* p) {
    u32 a;
    asm("{ .reg .u64 t; cvta.to.shared.u64 t, %1; cvt.u32.u64 %0, t; }" : "=r"(a) : "l"(p));
    return a;
}
__device__ __forceinline__ void cp16(u32 dst, const void* src) {
    asm volatile("cp.async.cg.shared.global [%0], [%1], 16;" :: "r"(dst), "l"(src));
}
#define CP_COMMIT() asm volatile("cp.async.commit_group;" ::: "memory")
#define CP_WAIT1()  asm volatile("cp.async.wait_group 1;" ::: "memory")
#define CP_WAIT0()  asm volatile("cp.async.wait_group 0;" ::: "memory")

#define LDX4(r, addr) \
    asm volatile("ldmatrix.sync.aligned.m8n8.x4.shared.b16 {%0,%1,%2,%3}, [%4];" \
        : "=r"((r)[0]), "=r"((r)[1]), "=r"((r)[2]), "=r"((r)[3]) : "r"(addr))
#define LDX4T(r, addr) \
    asm volatile("ldmatrix.sync.aligned.m8n8.x4.trans.shared.b16 {%0,%1,%2,%3}, [%4];" \
        : "=r"((r)[0]), "=r"((r)[1]), "=r"((r)[2]), "=r"((r)[3]) : "r"(addr))

#define MMA16816(d, a, b0, b1) \
    asm volatile("mma.sync.aligned.m16n8k16.row.col.f32.bf16.bf16.f32 " \
        "{%0,%1,%2,%3}, {%4,%5,%6,%7}, {%8,%9}, {%0,%1,%2,%3};" \
        : "+f"((d)[0]), "+f"((d)[1]), "+f"((d)[2]), "+f"((d)[3]) \
        : "r"((a)[0]), "r"((a)[1]), "r"((a)[2]), "r"((a)[3]), "r"(b0), "r"(b1))

// split v0,v1 (fp32) -> packed bf16x2 hi + lo residual
__device__ __forceinline__ void split_pack(float v0, float v1, u32& h, u32& l) {
    __nv_bfloat162 hb = __floats2bfloat162_rn(v0, v1);
    h = *reinterpret_cast<u32*>(&hb);
    float r0 = v0 - __low2float(hb);
    float r1 = v1 - __high2float(hb);
    __nv_bfloat162 lb = __floats2bfloat162_rn(r0, r1);
    l = *reinterpret_cast<u32*>(&lb);
}

// ---------------------------------------------------------------------------
// Split kernels: fp32 -> (hi, lo) bf16
// ---------------------------------------------------------------------------
__global__ void split_rm(const float* __restrict__ src, int n4)
{
    __nv_bfloat16* hi = g_ah;
    __nv_bfloat16* lo = g_al;
    for (int i = blockIdx.x * blockDim.x + threadIdx.x; i < n4; i += gridDim.x * blockDim.x) {
        float4 v = reinterpret_cast<const float4*>(src)[i];
        uint2 hv, lv;
        split_pack(v.x, v.y, hv.x, lv.x);
        split_pack(v.z, v.w, hv.y, lv.y);
        reinterpret_cast<uint2*>(hi)[i] = hv;
        reinterpret_cast<uint2*>(lo)[i] = lv;
    }
}

// W [Kd, Nd] row-major -> hi/lo [Nd, Kd]. MODE 0 -> g_wqh/g_wql, MODE 1 -> g_woh/g_wol.
template <int MODE>
__global__ void split_tr(const float* __restrict__ W, int Kd, int Nd)
{
    __nv_bfloat16* hi = (MODE == 0) ? g_wqh : g_woh;
    __nv_bfloat16* lo = (MODE == 0) ? g_wql : g_wol;
    __shared__ float t[32][33];
    const int n0 = blockIdx.x * 32, k0 = blockIdx.y * 32;
    const int tx = threadIdx.x, ty = threadIdx.y;
#pragma unroll
    for (int i = 0; i < 4; i++)
        t[ty + i * 8][tx] = W[(size_t)(k0 + ty + i * 8) * Nd + n0 + tx];
    __syncthreads();
#pragma unroll
    for (int i = 0; i < 4; i++) {
        const int nn = ty + i * 8;
        float v = t[tx][nn];
        __nv_bfloat16 h = __float2bfloat16_rn(v);
        __nv_bfloat16 l = __float2bfloat16_rn(v - __bfloat162float(h));
        hi[(size_t)(n0 + nn) * Kd + k0 + tx] = h;
        lo[(size_t)(n0 + nn) * Kd + k0 + tx] = l;
    }
}

// ---------------------------------------------------------------------------
// mma.sync bf16-split GEMM. Product-major mma ordering (no same-acc chains).
// MODE 0: epilogue -> bf16 hi/lo Q(scaled)/K/V.  MODE 1: fp32 + bias -> C.
// ---------------------------------------------------------------------------
#define KC        64
#define TILE_B    16384
#define OFF_AH    0
#define OFF_AL    TILE_B
#define OFF_BH    (2 * TILE_B)
#define OFF_BL    (3 * TILE_B)
#define STAGE_B   (4 * TILE_B)
#define GEMM_SMEM (2 * STAGE_B)

__device__ __forceinline__ void load_chunk(u32 stg,
    const __nv_bfloat16* __restrict__ Ah, const __nv_bfloat16* __restrict__ Al,
    const __nv_bfloat16* __restrict__ Bh, const __nv_bfloat16* __restrict__ Bl,
    int bm, int bn, int col0, int K, int tid)
{
#pragma unroll
    for (int i = 0; i < 4; i++) {
        const int idx = i * 256 + tid;
        const int r = idx >> 3, cc = idx & 7;
        u32 off = (u32)((r << 7) + (cc << 4));
        off ^= (off >> 3) & 0x70;
        const size_t aoff = (size_t)(bm + r) * K + col0 + cc * 8;
        const size_t boff = (size_t)(bn + r) * K + col0 + cc * 8;
        cp16(stg + OFF_AH + off, Ah + aoff);
        cp16(stg + OFF_AL + off, Al + aoff);
        cp16(stg + OFF_BH + off, Bh + boff);
        cp16(stg + OFF_BL + off, Bl + boff);
    }
}

template <int MODE>
__global__ __launch_bounds__(256, 1)
void gemm_mma(const float* __restrict__ bias, float* __restrict__ C, int N, int K)
{
    const __nv_bfloat16* Ah = g_ah;
    const __nv_bfloat16* Al = g_al;
    const __nv_bfloat16* Bh = (MODE == 0) ? g_wqh : g_woh;
    const __nv_bfloat16* Bl = (MODE == 0) ? g_wql : g_wol;

    extern __shared__ char smem[];
    const u32 sbase = smem_u32_of(smem);
    const int tid = threadIdx.x;
    const int bm = blockIdx.y * 128;
    const int bn = blockIdx.x * 128;
    const int lane = tid & 31, warp = tid >> 5;
    const int m0w = (warp >> 2) * 64;
    const int n0w = (warp & 3) * 32;

    float acc[4][4][4];
#pragma unroll
    for (int mi = 0; mi < 4; mi++)
#pragma unroll
        for (int ni = 0; ni < 4; ni++)
#pragma unroll
            for (int q = 0; q < 4; q++) acc[mi][ni][q] = 0.f;

    const int aRowOff = lane & 15;
    const u32 aKb = (u32)((lane >> 4) << 4);
    const int bRowOff = ((lane >> 4) & 1) * 8 + (lane & 7);
    const u32 bKb = (u32)(((lane >> 3) & 1) << 4);

    const int NC = K / KC;

    load_chunk(sbase, Ah, Al, Bh, Bl, bm, bn, 0, K, tid);
    CP_COMMIT();

    for (int c = 0; c < NC; c++) {
        const u32 stg = sbase + (u32)(c & 1) * STAGE_B;
        if (c + 1 < NC) {
            load_chunk(sbase + (u32)((c + 1) & 1) * STAGE_B, Ah, Al, Bh, Bl, bm, bn, (c + 1) * KC, K, tid);
            CP_COMMIT();
            CP_WAIT1();
        } else {
            CP_WAIT0();
        }
        __syncthreads();

#pragma unroll
        for (int k16 = 0; k16 < 4; k16++) {
            u32 fAh[4][4], fAl[4][4];
#pragma unroll
            for (int mi = 0; mi < 4; mi++) {
                u32 off = (u32)(m0w + mi * 16 + aRowOff) * 128 + aKb + (u32)k16 * 32;
                off ^= (off >> 3) & 0x70;
                LDX4(fAh[mi], stg + OFF_AH + off);
                LDX4(fAl[mi], stg + OFF_AL + off);
            }
            u32 fBh[2][4], fBl[2][4];
#pragma unroll
            for (int bi = 0; bi < 2; bi++) {
                u32 off = (u32)(n0w + bi * 16 + bRowOff) * 128 + bKb + (u32)k16 * 32;
                off ^= (off >> 3) & 0x70;
                LDX4(fBh[bi], stg + OFF_BH + off);
                LDX4(fBl[bi], stg + OFF_BL + off);
            }
            // product-major: 16 independent accumulators between same-acc reuse
#pragma unroll
            for (int mi = 0; mi < 4; mi++)
#pragma unroll
                for (int ni = 0; ni < 4; ni++)
                    MMA16816(acc[mi][ni], fAh[mi],
                             fBh[ni >> 1][(ni & 1) * 2], fBh[ni >> 1][(ni & 1) * 2 + 1]);
#pragma unroll
            for (int mi = 0; mi < 4; mi++)
#pragma unroll
                for (int ni = 0; ni < 4; ni++)
                    MMA16816(acc[mi][ni], fAh[mi],
                             fBl[ni >> 1][(ni & 1) * 2], fBl[ni >> 1][(ni & 1) * 2 + 1]);
#pragma unroll
            for (int mi = 0; mi < 4; mi++)
#pragma unroll
                for (int ni = 0; ni < 4; ni++)
                    MMA16816(acc[mi][ni], fAl[mi],
                             fBh[ni >> 1][(ni & 1) * 2], fBh[ni >> 1][(ni & 1) * 2 + 1]);
        }
        __syncthreads();
    }

#pragma unroll
    for (int ni = 0; ni < 4; ni++) {
        const int g = bn + n0w + ni * 8 + (lane & 3) * 2;
        const float bv0 = bias[g], bv1 = bias[g + 1];
        if (MODE == 1) {
#pragma unroll
            for (int mi = 0; mi < 4; mi++) {
                const int r0 = bm + m0w + mi * 16 + (lane >> 2);
                float2 v0 = {acc[mi][ni][0] + bv0, acc[mi][ni][1] + bv1};
                float2 v1 = {acc[mi][ni][2] + bv0, acc[mi][ni][3] + bv1};
                *reinterpret_cast<float2*>(C + (size_t)r0 * N + g) = v0;
                *reinterpret_cast<float2*>(C + (size_t)(r0 + 8) * N + g) = v1;
            }
        } else {
            const int qkv = g >> 10;
            const int h = (g & 1023) >> 6;
            const int c0 = g & 63;
            const float scl = (qkv == 0) ? SCALE : 1.f;
            __nv_bfloat16* hb = (qkv == 0) ? g_qh : ((qkv == 1) ? g_kh : g_vh);
            __nv_bfloat16* lb = (qkv == 0) ? g_ql : ((qkv == 1) ? g_kl : g_vl);
#pragma unroll
            for (int mi = 0; mi < 4; mi++) {
#pragma unroll
                for (int half = 0; half < 2; half++) {
                    const int row = bm + m0w + mi * 16 + (lane >> 2) + half * 8;
                    const int b = row >> 11;
                    const int sI = row & (Sc - 1);
                    const float v0 = (acc[mi][ni][half * 2 + 0] + bv0) * scl;
                    const float v1 = (acc[mi][ni][half * 2 + 1] + bv1) * scl;
                    u32 hv, lv;
                    split_pack(v0, v1, hv, lv);
                    const size_t o = (((size_t)(b * Hc + h)) * Sc + sI) * HDc + c0;
                    *reinterpret_cast<u32*>(hb + o) = hv;
                    *reinterpret_cast<u32*>(lb + o) = lv;
                }
            }
        }
    }
}

// ---------------------------------------------------------------------------
// FlashAttention-2 with mma.sync, product-major ordering.
// CTA = 128 queries, 8 warps (16 rows each). Key tiles of 64.
// ---------------------------------------------------------------------------
#define A_QH   0
#define A_QL   16384
#define A_STG  32768            // 2 stages x 32768: {KH, KL, VH, VL} x 8192
#define ATT_SMEM (32768 + 2 * 32768)   // 96 KB

__device__ __forceinline__ void attn_load_stage(u32 stg,
    const __nv_bfloat16* Kh, const __nv_bfloat16* Kl,
    const __nv_bfloat16* Vh, const __nv_bfloat16* Vl, int kt, int tid)
{
#pragma unroll
    for (int i = 0; i < 8; i++) {
        const int idx = i * 256 + tid;
        const int tile = idx >> 9;
        const int r = (idx >> 3) & 63;
        const int cc = idx & 7;
        u32 off = (u32)(r * 128 + cc * 16);
        off ^= (off >> 3) & 0x70;
        const __nv_bfloat16* s = (tile == 0) ? Kh : ((tile == 1) ? Kl : ((tile == 2) ? Vh : Vl));
        cp16(stg + (u32)tile * 8192 + off, s + (size_t)(kt * 64 + r) * HDc + cc * 8);
    }
}

__global__ __launch_bounds__(256, 1)
void attn_mma()
{
    const int bh = blockIdx.y;
    const int qb = (int)gridDim.x - 1 - (int)blockIdx.x;   // big tiles first
    const int b = bh >> 4, h = bh & 15;

    extern __shared__ char smem[];
    const u32 sb = smem_u32_of(smem);
    const int tid = threadIdx.x, lane = tid & 31, warp = tid >> 5;
    const int m0w = warp * 16;

    const size_t bhoff = (size_t)bh * Sc * HDc;
    const __nv_bfloat16* Qh = g_qh + bhoff;
    const __nv_bfloat16* Ql = g_ql + bhoff;
    const __nv_bfloat16* Kh = g_kh + bhoff;
    const __nv_bfloat16* Kl = g_kl + bhoff;
    const __nv_bfloat16* Vh = g_vh + bhoff;
    const __nv_bfloat16* Vl = g_vl + bhoff;

    const int NT = 2 * qb + 2;

    // preload Q tile (hi+lo) + stage 0
#pragma unroll
    for (int i = 0; i < 8; i++) {
        const int idx = i * 256 + tid;
        const int hl = idx >> 10;
        const int r = (idx >> 3) & 127;
        const int cc = idx & 7;
        u32 off = (u32)(r * 128 + cc * 16);
        off ^= (off >> 3) & 0x70;
        const __nv_bfloat16* s = hl ? Ql : Qh;
        cp16(sb + (hl ? A_QL : A_QH) + off, s + (size_t)(qb * 128 + r) * HDc + cc * 8);
    }
    attn_load_stage(sb + A_STG, Kh, Kl, Vh, Vl, 0, tid);
    CP_COMMIT();

    const int aRowOff = lane & 15;
    const u32 aKb = (u32)((lane >> 4) << 4);
    const int bRowOff = ((lane >> 4) & 1) * 8 + (lane & 7);
    const u32 bKb = (u32)(((lane >> 3) & 1) << 4);

    u32 qfh[4][4], qfl[4][4];
    float oacc[8][4];
#pragma unroll
    for (int ni = 0; ni < 8; ni++)
#pragma unroll
        for (int q = 0; q < 4; q++) oacc[ni][q] = 0.f;
    float m0 = NEGINF, m1 = NEGINF, l0 = 0.f, l1 = 0.f;

    const int qi0 = qb * 128 + m0w + (lane >> 2);

    for (int c = 0; c < NT; c++) {
        const u32 stg = sb + A_STG + (u32)(c & 1) * 32768;
        if (c + 1 < NT) {
            attn_load_stage(sb + A_STG + (u32)((c + 1) & 1) * 32768, Kh, Kl, Vh, Vl, c + 1, tid);
            CP_COMMIT();
            CP_WAIT1();
        } else {
            CP_WAIT0();
        }
        __syncthreads();

        if (c == 0) {
#pragma unroll
            for (int kk = 0; kk < 4; kk++) {
                u32 off = (u32)(m0w + aRowOff) * 128 + aKb + (u32)kk * 32;
                off ^= (off >> 3) & 0x70;
                LDX4(qfh[kk], sb + A_QH + off);
                LDX4(qfl[kk], sb + A_QL + off);
            }
        }

        // ---- S = Q K^T (product-major) ----
        float sacc[8][4];
#pragma unroll
        for (int ni = 0; ni < 8; ni++)
#pragma unroll
            for (int q = 0; q < 4; q++) sacc[ni][q] = 0.f;

#pragma unroll
        for (int kk = 0; kk < 4; kk++) {
            u32 fkh[4][4], fkl[4][4];
#pragma unroll
            for (int g = 0; g < 4; g++) {
                u32 off = (u32)(g * 16 + bRowOff) * 128 + bKb + (u32)kk * 32;
                off ^= (off >> 3) & 0x70;
                LDX4(fkh[g], stg + 0 + off);
                LDX4(fkl[g], stg + 8192 + off);
            }
#pragma unroll
            for (int ni = 0; ni < 8; ni++)
                MMA16816(sacc[ni], qfh[kk],
                         fkh[ni >> 1][(ni & 1) * 2], fkh[ni >> 1][(ni & 1) * 2 + 1]);
#pragma unroll
            for (int ni = 0; ni < 8; ni++)
                MMA16816(sacc[ni], qfl[kk],
                         fkh[ni >> 1][(ni & 1) * 2], fkh[ni >> 1][(ni & 1) * 2 + 1]);
#pragma unroll
            for (int ni = 0; ni < 8; ni++)
                MMA16816(sacc[ni], qfh[kk],
                         fkl[ni >> 1][(ni & 1) * 2], fkl[ni >> 1][(ni & 1) * 2 + 1]);
        }

        // ---- causal mask (only last two tiles) ----
        if (c >= 2 * qb) {
#pragma unroll
            for (int ni = 0; ni < 8; ni++) {
                const int col = c * 64 + ni * 8 + (lane & 3) * 2;
                if (col > qi0)     sacc[ni][0] = NEGINF;
                if (col + 1 > qi0) sacc[ni][1] = NEGINF;
                if (col > qi0 + 8)     sacc[ni][2] = NEGINF;
                if (col + 1 > qi0 + 8) sacc[ni][3] = NEGINF;
            }
        }

        // ---- online softmax ----
        float mx0 = NEGINF, mx1 = NEGINF;
#pragma unroll
        for (int ni = 0; ni < 8; ni++) {
            mx0 = fmaxf(mx0, fmaxf(sacc[ni][0], sacc[ni][1]));
            mx1 = fmaxf(mx1, fmaxf(sacc[ni][2], sacc[ni][3]));
        }
        mx0 = fmaxf(mx0, __shfl_xor_sync(0xffffffffu, mx0, 1));
        mx0 = fmaxf(mx0, __shfl_xor_sync(0xffffffffu, mx0, 2));
        mx1 = fmaxf(mx1, __shfl_xor_sync(0xffffffffu, mx1, 1));
        mx1 = fmaxf(mx1, __shfl_xor_sync(0xffffffffu, mx1, 2));

        const float nm0 = fmaxf(m0, mx0), nm1 = fmaxf(m1, mx1);
        const float cr0 = __expf(m0 - nm0), cr1 = __expf(m1 - nm1);
        m0 = nm0; m1 = nm1;

        float s0 = 0.f, s1 = 0.f;
#pragma unroll
        for (int ni = 0; ni < 8; ni++) {
            sacc[ni][0] = __expf(sacc[ni][0] - nm0);
            sacc[ni][1] = __expf(sacc[ni][1] - nm0);
            sacc[ni][2] = __expf(sacc[ni][2] - nm1);
            sacc[ni][3] = __expf(sacc[ni][3] - nm1);
            s0 += sacc[ni][0] + sacc[ni][1];
            s1 += sacc[ni][2] + sacc[ni][3];
        }
        s0 += __shfl_xor_sync(0xffffffffu, s0, 1);
        s0 += __shfl_xor_sync(0xffffffffu, s0, 2);
        s1 += __shfl_xor_sync(0xffffffffu, s1, 1);
        s1 += __shfl_xor_sync(0xffffffffu, s1, 2);
        l0 = l0 * cr0 + s0;
        l1 = l1 * cr1 + s1;

#pragma unroll
        for (int ni = 0; ni < 8; ni++) {
            oacc[ni][0] *= cr0; oacc[ni][1] *= cr0;
            oacc[ni][2] *= cr1; oacc[ni][3] *= cr1;
        }

        // ---- O += P V (product-major over 8 accumulators) ----
#pragma unroll
        for (int kk = 0; kk < 4; kk++) {
            u32 ph[4], pl[4];
            split_pack(sacc[2 * kk][0],     sacc[2 * kk][1],     ph[0], pl[0]);
            split_pack(sacc[2 * kk][2],     sacc[2 * kk][3],     ph[1], pl[1]);
            split_pack(sacc[2 * kk + 1][0], sacc[2 * kk + 1][1], ph[2], pl[2]);
            split_pack(sacc[2 * kk + 1][2], sacc[2 * kk + 1][3], ph[3], pl[3]);
            u32 fvh[4][4], fvl[4][4];
#pragma unroll
            for (int nj = 0; nj < 4; nj++) {
                u32 off = (u32)(kk * 16 + (lane & 15)) * 128 + (u32)nj * 32 + (u32)((lane >> 4) << 4);
                off ^= (off >> 3) & 0x70;
                LDX4T(fvh[nj], stg + 16384 + off);
                LDX4T(fvl[nj], stg + 24576 + off);
            }
#pragma unroll
            for (int nj = 0; nj < 4; nj++) {
                MMA16816(oacc[nj * 2 + 0], ph, fvh[nj][0], fvh[nj][1]);
                MMA16816(oacc[nj * 2 + 1], ph, fvh[nj][2], fvh[nj][3]);
            }
#pragma unroll
            for (int nj = 0; nj < 4; nj++) {
                MMA16816(oacc[nj * 2 + 0], pl, fvh[nj][0], fvh[nj][1]);
                MMA16816(oacc[nj * 2 + 1], pl, fvh[nj][2], fvh[nj][3]);
            }
#pragma unroll
            for (int nj = 0; nj < 4; nj++) {
                MMA16816(oacc[nj * 2 + 0], ph, fvl[nj][0], fvl[nj][1]);
                MMA16816(oacc[nj * 2 + 1], ph, fvl[nj][2], fvl[nj][3]);
            }
        }
        __syncthreads();
    }

    // ---- epilogue: normalize, split hi/lo, write to g_ah/g_al ----
    const float inv0 = 1.f / l0, inv1 = 1.f / l1;
    const size_t r0off = ((size_t)b * Sc + qi0) * Dc + h * HDc;
    const size_t r1off = ((size_t)b * Sc + qi0 + 8) * Dc + h * HDc;
#pragma unroll
    for (int ni = 0; ni < 8; ni++) {
        const int col = ni * 8 + (lane & 3) * 2;
        u32 hv, lv;
        split_pack(oacc[ni][0] * inv0, oacc[ni][1] * inv0, hv, lv);
        *reinterpret_cast<u32*>(g_ah + r0off + col) = hv;
        *reinterpret_cast<u32*>(g_al + r0off + col) = lv;
        split_pack(oacc[ni][2] * inv1, oacc[ni][3] * inv1, hv, lv);
        *reinterpret_cast<u32*>(g_ah + r1off + col) = hv;
        *reinterpret_cast<u32*>(g_al + r1off + col) = lv;
    }
}

// ---------------------------------------------------------------------------
extern "C" void kernel_launch(void* const* d_in, const int* in_sizes, int n_in,
                              void* d_out, int out_size)
{
    const float* X     = (const float*)d_in[0];
    const float* W_qkv = (const float*)d_in[1];
    const float* b_qkv = (const float*)d_in[2];
    const float* W_out = (const float*)d_in[3];
    const float* b_out = (const float*)d_in[4];
    float* out = (float*)d_out;

    cudaFuncSetAttribute(gemm_mma<0>, cudaFuncAttributeMaxDynamicSharedMemorySize, GEMM_SMEM);
    cudaFuncSetAttribute(gemm_mma<1>, cudaFuncAttributeMaxDynamicSharedMemorySize, GEMM_SMEM);
    cudaFuncSetAttribute(attn_mma, cudaFuncAttributeMaxDynamicSharedMemorySize, ATT_SMEM);

    // bf16 splits
    split_rm<<<1024, 256>>>(X, Mtot * Dc / 4);
    split_tr<0><<<dim3(3 * Dc / 32, Dc / 32), dim3(32, 8)>>>(W_qkv, Dc, 3 * Dc);
    split_tr<1><<<dim3(Dc / 32, Dc / 32), dim3(32, 8)>>>(W_out, Dc, Dc);

    // 1) QKV projection -> bf16 hi/lo Q(scaled)/K/V in [bh,s,hd]
    gemm_mma<0><<<dim3(3 * Dc / 128, Mtot / 128), 256, GEMM_SMEM>>>(b_qkv, nullptr, 3 * Dc, Dc);

    // 2) causal flash attention (tensor cores) -> g_ah/g_al (hi/lo, [b,s,D])
    attn_mma<<<dim3(Sc / 128, Bc * Hc), 256, ATT_SMEM>>>();

    // 3) out-proj -> d_out
    gemm_mma<1><<<dim3(Dc / 128, Mtot / 128), 256, GEMM_SMEM>>>(b_out, out, Dc, Dc);
}

// round 8
// speedup vs baseline: 1.0392x; 1.0392x over previous
#include <cuda_runtime.h>
#include <cuda_bf16.h>
#include <math.h>
#include <stdint.h>

// Problem constants
#define Bc   2
#define Sc   2048
#define Dc   1024
#define Hc   16
#define HDc  64
#define Mtot 4096
#define SCALE 0.03125f          // 1/sqrt(1024)
#define NEGINF (-1e30f)

typedef unsigned long long u64;
typedef uint32_t u32;

// ---------------- scratch (device globals; referenced ONLY in device code) --
__device__ __nv_bfloat16 g_qh[(size_t)Bc * Hc * Sc * HDc];   // [bh, s, hd], pre-scaled
__device__ __nv_bfloat16 g_ql[(size_t)Bc * Hc * Sc * HDc];
__device__ __nv_bfloat16 g_kh[(size_t)Bc * Hc * Sc * HDc];
__device__ __nv_bfloat16 g_kl[(size_t)Bc * Hc * Sc * HDc];
__device__ __nv_bfloat16 g_vh[(size_t)Bc * Hc * Sc * HDc];
__device__ __nv_bfloat16 g_vl[(size_t)Bc * Hc * Sc * HDc];

__device__ __nv_bfloat16 g_ah[(size_t)Mtot * Dc];      // A hi (X, then attn out)
__device__ __nv_bfloat16 g_al[(size_t)Mtot * Dc];
__device__ __nv_bfloat16 g_wqh[(size_t)3 * Dc * Dc];   // W_qkv^T hi  [3072, 1024]
__device__ __nv_bfloat16 g_wql[(size_t)3 * Dc * Dc];
__device__ __nv_bfloat16 g_woh[(size_t)Dc * Dc];       // W_out^T hi  [1024, 1024]
__device__ __nv_bfloat16 g_wol[(size_t)Dc * Dc];

// ---------------- PTX helpers (non-arch-specific, sm_80 class) --------------
__device__ __forceinline__ u32 smem_u32_of(const void* p) {
    u32 a;
    asm("{ .reg .u64 t; cvta.to.shared.u64 t, %1; cvt.u32.u64 %0, t; }" : "=r"(a) : "l"(p));
    return a;
}
__device__ __forceinline__ void cp16(u32 dst, const void* src) {
    asm volatile("cp.async.cg.shared.global [%0], [%1], 16;" :: "r"(dst), "l"(src));
}
#define CP_COMMIT() asm volatile("cp.async.commit_group;" ::: "memory")
#define CP_WAIT1()  asm volatile("cp.async.wait_group 1;" ::: "memory")
#define CP_WAIT0()  asm volatile("cp.async.wait_group 0;" ::: "memory")

#define LDX4(r, addr) \
    asm volatile("ldmatrix.sync.aligned.m8n8.x4.shared.b16 {%0,%1,%2,%3}, [%4];" \
        : "=r"((r)[0]), "=r"((r)[1]), "=r"((r)[2]), "=r"((r)[3]) : "r"(addr))
#define LDX4T(r, addr) \
    asm volatile("ldmatrix.sync.aligned.m8n8.x4.trans.shared.b16 {%0,%1,%2,%3}, [%4];" \
        : "=r"((r)[0]), "=r"((r)[1]), "=r"((r)[2]), "=r"((r)[3]) : "r"(addr))

#define MMA16816(d, a, b0, b1) \
    asm volatile("mma.sync.aligned.m16n8k16.row.col.f32.bf16.bf16.f32 " \
        "{%0,%1,%2,%3}, {%4,%5,%6,%7}, {%8,%9}, {%0,%1,%2,%3};" \
        : "+f"((d)[0]), "+f"((d)[1]), "+f"((d)[2]), "+f"((d)[3]) \
        : "r"((a)[0]), "r"((a)[1]), "r"((a)[2]), "r"((a)[3]), "r"(b0), "r"(b1))

// split v0,v1 (fp32) -> packed bf16x2 hi + lo residual
__device__ __forceinline__ void split_pack(float v0, float v1, u32& h, u32& l) {
    __nv_bfloat162 hb = __floats2bfloat162_rn(v0, v1);
    h = *reinterpret_cast<u32*>(&hb);
    float r0 = v0 - __low2float(hb);
    float r1 = v1 - __high2float(hb);
    __nv_bfloat162 lb = __floats2bfloat162_rn(r0, r1);
    l = *reinterpret_cast<u32*>(&lb);
}

// ---------------------------------------------------------------------------
// Split kernels: fp32 -> (hi, lo) bf16
// ---------------------------------------------------------------------------
__global__ void split_rm(const float* __restrict__ src, int n4)
{
    __nv_bfloat16* hi = g_ah;
    __nv_bfloat16* lo = g_al;
    for (int i = blockIdx.x * blockDim.x + threadIdx.x; i < n4; i += gridDim.x * blockDim.x) {
        float4 v = reinterpret_cast<const float4*>(src)[i];
        uint2 hv, lv;
        split_pack(v.x, v.y, hv.x, lv.x);
        split_pack(v.z, v.w, hv.y, lv.y);
        reinterpret_cast<uint2*>(hi)[i] = hv;
        reinterpret_cast<uint2*>(lo)[i] = lv;
    }
}

// W [Kd, Nd] row-major -> hi/lo [Nd, Kd]. MODE 0 -> g_wqh/g_wql, MODE 1 -> g_woh/g_wol.
template <int MODE>
__global__ void split_tr(const float* __restrict__ W, int Kd, int Nd)
{
    __nv_bfloat16* hi = (MODE == 0) ? g_wqh : g_woh;
    __nv_bfloat16* lo = (MODE == 0) ? g_wql : g_wol;
    __shared__ float t[32][33];
    const int n0 = blockIdx.x * 32, k0 = blockIdx.y * 32;
    const int tx = threadIdx.x, ty = threadIdx.y;
#pragma unroll
    for (int i = 0; i < 4; i++)
        t[ty + i * 8][tx] = W[(size_t)(k0 + ty + i * 8) * Nd + n0 + tx];
    __syncthreads();
#pragma unroll
    for (int i = 0; i < 4; i++) {
        const int nn = ty + i * 8;
        float v = t[tx][nn];
        __nv_bfloat16 h = __float2bfloat16_rn(v);
        __nv_bfloat16 l = __float2bfloat16_rn(v - __bfloat162float(h));
        hi[(size_t)(n0 + nn) * Kd + k0 + tx] = h;
        lo[(size_t)(n0 + nn) * Kd + k0 + tx] = l;
    }
}

// ---------------------------------------------------------------------------
// mma.sync bf16-split GEMM, 2 CTAs/SM. Tile 128x64, 8 warps (4x2), warp 32x32.
// MODE 0: epilogue -> bf16 hi/lo Q(scaled)/K/V.  MODE 1: fp32 + bias -> C.
// ---------------------------------------------------------------------------
#define KC        64
#define OFF_AH    0
#define OFF_AL    16384
#define OFF_BH    32768
#define OFF_BL    40960
#define STAGE_B   49152          // 48 KB
#define GEMM_SMEM (2 * STAGE_B)  // 96 KB -> 2 CTAs/SM

__device__ __forceinline__ void load_chunk(u32 stg,
    const __nv_bfloat16* __restrict__ Ah, const __nv_bfloat16* __restrict__ Al,
    const __nv_bfloat16* __restrict__ Bh, const __nv_bfloat16* __restrict__ Bl,
    int bm, int bn, int col0, int K, int tid)
{
    // A: 128 rows x 64 bf16 (hi+lo) = 2048 vec16 ; B: 64 rows (hi+lo) = 1024 vec16
#pragma unroll
    for (int i = 0; i < 8; i++) {
        const int idx = i * 256 + tid;
        const int hl = idx >> 10;            // constant per i
        const int r = (idx >> 3) & 127;
        const int cc = idx & 7;
        u32 off = (u32)((r << 7) + (cc << 4));
        off ^= (off >> 3) & 0x70;
        const __nv_bfloat16* s = hl ? Al : Ah;
        cp16(stg + (hl ? OFF_AL : OFF_AH) + off, s + (size_t)(bm + r) * K + col0 + cc * 8);
    }
#pragma unroll
    for (int i = 0; i < 4; i++) {
        const int idx = i * 256 + tid;
        const int hl = i >> 1;               // constant per i
        const int r = (idx >> 3) & 63;
        const int cc = idx & 7;
        u32 off = (u32)((r << 7) + (cc << 4));
        off ^= (off >> 3) & 0x70;
        const __nv_bfloat16* s = hl ? Bl : Bh;
        cp16(stg + (hl ? OFF_BL : OFF_BH) + off, s + (size_t)(bn + r) * K + col0 + cc * 8);
    }
}

template <int MODE>
__global__ __launch_bounds__(256, 2)
void gemm_mma(const float* __restrict__ bias, float* __restrict__ C, int N, int K)
{
    const __nv_bfloat16* Ah = g_ah;
    const __nv_bfloat16* Al = g_al;
    const __nv_bfloat16* Bh = (MODE == 0) ? g_wqh : g_woh;
    const __nv_bfloat16* Bl = (MODE == 0) ? g_wql : g_wol;

    extern __shared__ char smem[];
    const u32 sbase = smem_u32_of(smem);
    const int tid = threadIdx.x;
    const int bm = blockIdx.y * 128;
    const int bn = blockIdx.x * 64;
    const int lane = tid & 31, warp = tid >> 5;
    const int m0w = (warp >> 1) * 32;        // 0,32,64,96
    const int n0w = (warp & 1) * 32;         // 0,32

    float acc[2][4][4];
#pragma unroll
    for (int mi = 0; mi < 2; mi++)
#pragma unroll
        for (int ni = 0; ni < 4; ni++)
#pragma unroll
            for (int q = 0; q < 4; q++) acc[mi][ni][q] = 0.f;

    const int aRowOff = lane & 15;
    const u32 aKb = (u32)((lane >> 4) << 4);
    const int bRowOff = ((lane >> 4) & 1) * 8 + (lane & 7);
    const u32 bKb = (u32)(((lane >> 3) & 1) << 4);

    const int NC = K / KC;

    load_chunk(sbase, Ah, Al, Bh, Bl, bm, bn, 0, K, tid);
    CP_COMMIT();

    for (int c = 0; c < NC; c++) {
        const u32 stg = sbase + (u32)(c & 1) * STAGE_B;
        if (c + 1 < NC) {
            load_chunk(sbase + (u32)((c + 1) & 1) * STAGE_B, Ah, Al, Bh, Bl, bm, bn, (c + 1) * KC, K, tid);
            CP_COMMIT();
            CP_WAIT1();
        } else {
            CP_WAIT0();
        }
        __syncthreads();

#pragma unroll
        for (int k16 = 0; k16 < 4; k16++) {
            u32 fAh[2][4], fAl[2][4];
#pragma unroll
            for (int mi = 0; mi < 2; mi++) {
                u32 off = (u32)(m0w + mi * 16 + aRowOff) * 128 + aKb + (u32)k16 * 32;
                off ^= (off >> 3) & 0x70;
                LDX4(fAh[mi], stg + OFF_AH + off);
                LDX4(fAl[mi], stg + OFF_AL + off);
            }
            u32 fBh[2][4], fBl[2][4];
#pragma unroll
            for (int bi = 0; bi < 2; bi++) {
                u32 off = (u32)(n0w + bi * 16 + bRowOff) * 128 + bKb + (u32)k16 * 32;
                off ^= (off >> 3) & 0x70;
                LDX4(fBh[bi], stg + OFF_BH + off);
                LDX4(fBl[bi], stg + OFF_BL + off);
            }
#pragma unroll
            for (int mi = 0; mi < 2; mi++)
#pragma unroll
                for (int ni = 0; ni < 4; ni++)
                    MMA16816(acc[mi][ni], fAh[mi],
                             fBh[ni >> 1][(ni & 1) * 2], fBh[ni >> 1][(ni & 1) * 2 + 1]);
#pragma unroll
            for (int mi = 0; mi < 2; mi++)
#pragma unroll
                for (int ni = 0; ni < 4; ni++)
                    MMA16816(acc[mi][ni], fAh[mi],
                             fBl[ni >> 1][(ni & 1) * 2], fBl[ni >> 1][(ni & 1) * 2 + 1]);
#pragma unroll
            for (int mi = 0; mi < 2; mi++)
#pragma unroll
                for (int ni = 0; ni < 4; ni++)
                    MMA16816(acc[mi][ni], fAl[mi],
                             fBh[ni >> 1][(ni & 1) * 2], fBh[ni >> 1][(ni & 1) * 2 + 1]);
        }
        __syncthreads();
    }

#pragma unroll
    for (int ni = 0; ni < 4; ni++) {
        const int g = bn + n0w + ni * 8 + (lane & 3) * 2;
        const float bv0 = bias[g], bv1 = bias[g + 1];
        if (MODE == 1) {
#pragma unroll
            for (int mi = 0; mi < 2; mi++) {
                const int r0 = bm + m0w + mi * 16 + (lane >> 2);
                float2 v0 = {acc[mi][ni][0] + bv0, acc[mi][ni][1] + bv1};
                float2 v1 = {acc[mi][ni][2] + bv0, acc[mi][ni][3] + bv1};
                *reinterpret_cast<float2*>(C + (size_t)r0 * N + g) = v0;
                *reinterpret_cast<float2*>(C + (size_t)(r0 + 8) * N + g) = v1;
            }
        } else {
            const int qkv = g >> 10;
            const int h = (g & 1023) >> 6;
            const int c0 = g & 63;
            const float scl = (qkv == 0) ? SCALE : 1.f;
            __nv_bfloat16* hb = (qkv == 0) ? g_qh : ((qkv == 1) ? g_kh : g_vh);
            __nv_bfloat16* lb = (qkv == 0) ? g_ql : ((qkv == 1) ? g_kl : g_vl);
#pragma unroll
            for (int mi = 0; mi < 2; mi++) {
#pragma unroll
                for (int half = 0; half < 2; half++) {
                    const int row = bm + m0w + mi * 16 + (lane >> 2) + half * 8;
                    const int b = row >> 11;
                    const int sI = row & (Sc - 1);
                    const float v0 = (acc[mi][ni][half * 2 + 0] + bv0) * scl;
                    const float v1 = (acc[mi][ni][half * 2 + 1] + bv1) * scl;
                    u32 hv, lv;
                    split_pack(v0, v1, hv, lv);
                    const size_t o = (((size_t)(b * Hc + h)) * Sc + sI) * HDc + c0;
                    *reinterpret_cast<u32*>(hb + o) = hv;
                    *reinterpret_cast<u32*>(lb + o) = lv;
                }
            }
        }
    }
}

// ---------------------------------------------------------------------------
// FlashAttention-2 with mma.sync, 2 CTAs/SM target (regs trimmed).
// CTA = 128 queries, 8 warps (16 rows each). Key tiles of 64.
// ---------------------------------------------------------------------------
#define A_QH   0
#define A_QL   16384
#define A_STG  32768            // 2 stages x 32768: {KH, KL, VH, VL} x 8192
#define ATT_SMEM (32768 + 2 * 32768)   // 96 KB -> 2 CTAs/SM

__device__ __forceinline__ void attn_load_stage(u32 stg,
    const __nv_bfloat16* Kh, const __nv_bfloat16* Kl,
    const __nv_bfloat16* Vh, const __nv_bfloat16* Vl, int kt, int tid)
{
#pragma unroll
    for (int i = 0; i < 8; i++) {
        const int idx = i * 256 + tid;
        const int tile = idx >> 9;
        const int r = (idx >> 3) & 63;
        const int cc = idx & 7;
        u32 off = (u32)(r * 128 + cc * 16);
        off ^= (off >> 3) & 0x70;
        const __nv_bfloat16* s = (tile == 0) ? Kh : ((tile == 1) ? Kl : ((tile == 2) ? Vh : Vl));
        cp16(stg + (u32)tile * 8192 + off, s + (size_t)(kt * 64 + r) * HDc + cc * 8);
    }
}

__global__ __launch_bounds__(256, 2)
void attn_mma()
{
    const int bh = blockIdx.y;
    const int qb = (int)gridDim.x - 1 - (int)blockIdx.x;   // big tiles first
    const int b = bh >> 4, h = bh & 15;

    extern __shared__ char smem[];
    const u32 sb = smem_u32_of(smem);
    const int tid = threadIdx.x, lane = tid & 31, warp = tid >> 5;
    const int m0w = warp * 16;

    const size_t bhoff = (size_t)bh * Sc * HDc;
    const __nv_bfloat16* Qh = g_qh + bhoff;
    const __nv_bfloat16* Ql = g_ql + bhoff;
    const __nv_bfloat16* Kh = g_kh + bhoff;
    const __nv_bfloat16* Kl = g_kl + bhoff;
    const __nv_bfloat16* Vh = g_vh + bhoff;
    const __nv_bfloat16* Vl = g_vl + bhoff;

    const int NT = 2 * qb + 2;

    // preload Q tile (hi+lo) + stage 0
#pragma unroll
    for (int i = 0; i < 8; i++) {
        const int idx = i * 256 + tid;
        const int hl = idx >> 10;
        const int r = (idx >> 3) & 127;
        const int cc = idx & 7;
        u32 off = (u32)(r * 128 + cc * 16);
        off ^= (off >> 3) & 0x70;
        const __nv_bfloat16* s = hl ? Ql : Qh;
        cp16(sb + (hl ? A_QL : A_QH) + off, s + (size_t)(qb * 128 + r) * HDc + cc * 8);
    }
    attn_load_stage(sb + A_STG, Kh, Kl, Vh, Vl, 0, tid);
    CP_COMMIT();

    const int aRowOff = lane & 15;
    const u32 aKb = (u32)((lane >> 4) << 4);
    const int bRowOff = ((lane >> 4) & 1) * 8 + (lane & 7);
    const u32 bKb = (u32)(((lane >> 3) & 1) << 4);

    float oacc[8][4];
#pragma unroll
    for (int ni = 0; ni < 8; ni++)
#pragma unroll
        for (int q = 0; q < 4; q++) oacc[ni][q] = 0.f;
    float m0 = NEGINF, m1 = NEGINF, l0 = 0.f, l1 = 0.f;

    const int qi0 = qb * 128 + m0w + (lane >> 2);

    for (int c = 0; c < NT; c++) {
        const u32 stg = sb + A_STG + (u32)(c & 1) * 32768;
        if (c + 1 < NT) {
            attn_load_stage(sb + A_STG + (u32)((c + 1) & 1) * 32768, Kh, Kl, Vh, Vl, c + 1, tid);
            CP_COMMIT();
            CP_WAIT1();
        } else {
            CP_WAIT0();
        }
        __syncthreads();

        // ---- S = Q K^T (Q frags loaded per k16 to cap register peak) ----
        float sacc[8][4];
#pragma unroll
        for (int ni = 0; ni < 8; ni++)
#pragma unroll
            for (int q = 0; q < 4; q++) sacc[ni][q] = 0.f;

#pragma unroll
        for (int kk = 0; kk < 4; kk++) {
            u32 qfh[4], qfl[4];
            {
                u32 off = (u32)(m0w + aRowOff) * 128 + aKb + (u32)kk * 32;
                off ^= (off >> 3) & 0x70;
                LDX4(qfh, sb + A_QH + off);
                LDX4(qfl, sb + A_QL + off);
            }
            u32 fkh[4][4], fkl[4][4];
#pragma unroll
            for (int g = 0; g < 4; g++) {
                u32 off = (u32)(g * 16 + bRowOff) * 128 + bKb + (u32)kk * 32;
                off ^= (off >> 3) & 0x70;
                LDX4(fkh[g], stg + 0 + off);
                LDX4(fkl[g], stg + 8192 + off);
            }
#pragma unroll
            for (int ni = 0; ni < 8; ni++)
                MMA16816(sacc[ni], qfh,
                         fkh[ni >> 1][(ni & 1) * 2], fkh[ni >> 1][(ni & 1) * 2 + 1]);
#pragma unroll
            for (int ni = 0; ni < 8; ni++)
                MMA16816(sacc[ni], qfl,
                         fkh[ni >> 1][(ni & 1) * 2], fkh[ni >> 1][(ni & 1) * 2 + 1]);
#pragma unroll
            for (int ni = 0; ni < 8; ni++)
                MMA16816(sacc[ni], qfh,
                         fkl[ni >> 1][(ni & 1) * 2], fkl[ni >> 1][(ni & 1) * 2 + 1]);
        }

        // ---- causal mask (only last two tiles) ----
        if (c >= 2 * qb) {
#pragma unroll
            for (int ni = 0; ni < 8; ni++) {
                const int col = c * 64 + ni * 8 + (lane & 3) * 2;
                if (col > qi0)     sacc[ni][0] = NEGINF;
                if (col + 1 > qi0) sacc[ni][1] = NEGINF;
                if (col > qi0 + 8)     sacc[ni][2] = NEGINF;
                if (col + 1 > qi0 + 8) sacc[ni][3] = NEGINF;
            }
        }

        // ---- online softmax ----
        float mx0 = NEGINF, mx1 = NEGINF;
#pragma unroll
        for (int ni = 0; ni < 8; ni++) {
            mx0 = fmaxf(mx0, fmaxf(sacc[ni][0], sacc[ni][1]));
            mx1 = fmaxf(mx1, fmaxf(sacc[ni][2], sacc[ni][3]));
        }
        mx0 = fmaxf(mx0, __shfl_xor_sync(0xffffffffu, mx0, 1));
        mx0 = fmaxf(mx0, __shfl_xor_sync(0xffffffffu, mx0, 2));
        mx1 = fmaxf(mx1, __shfl_xor_sync(0xffffffffu, mx1, 1));
        mx1 = fmaxf(mx1, __shfl_xor_sync(0xffffffffu, mx1, 2));

        const float nm0 = fmaxf(m0, mx0), nm1 = fmaxf(m1, mx1);
        const float cr0 = __expf(m0 - nm0), cr1 = __expf(m1 - nm1);
        m0 = nm0; m1 = nm1;

        float s0 = 0.f, s1 = 0.f;
#pragma unroll
        for (int ni = 0; ni < 8; ni++) {
            sacc[ni][0] = __expf(sacc[ni][0] - nm0);
            sacc[ni][1] = __expf(sacc[ni][1] - nm0);
            sacc[ni][2] = __expf(sacc[ni][2] - nm1);
            sacc[ni][3] = __expf(sacc[ni][3] - nm1);
            s0 += sacc[ni][0] + sacc[ni][1];
            s1 += sacc[ni][2] + sacc[ni][3];
        }
        s0 += __shfl_xor_sync(0xffffffffu, s0, 1);
        s0 += __shfl_xor_sync(0xffffffffu, s0, 2);
        s1 += __shfl_xor_sync(0xffffffffu, s1, 1);
        s1 += __shfl_xor_sync(0xffffffffu, s1, 2);
        l0 = l0 * cr0 + s0;
        l1 = l1 * cr1 + s1;

#pragma unroll
        for (int ni = 0; ni < 8; ni++) {
            oacc[ni][0] *= cr0; oacc[ni][1] *= cr0;
            oacc[ni][2] *= cr1; oacc[ni][3] *= cr1;
        }

        // ---- O += P V (V frags loaded per nj to cap register peak) ----
#pragma unroll
        for (int kk = 0; kk < 4; kk++) {
            u32 ph[4], pl[4];
            split_pack(sacc[2 * kk][0],     sacc[2 * kk][1],     ph[0], pl[0]);
            split_pack(sacc[2 * kk][2],     sacc[2 * kk][3],     ph[1], pl[1]);
            split_pack(sacc[2 * kk + 1][0], sacc[2 * kk + 1][1], ph[2], pl[2]);
            split_pack(sacc[2 * kk + 1][2], sacc[2 * kk + 1][3], ph[3], pl[3]);
#pragma unroll
            for (int nj = 0; nj < 4; nj++) {
                u32 fvh[4], fvl[4];
                u32 off = (u32)(kk * 16 + (lane & 15)) * 128 + (u32)nj * 32 + (u32)((lane >> 4) << 4);
                off ^= (off >> 3) & 0x70;
                LDX4T(fvh, stg + 16384 + off);
                LDX4T(fvl, stg + 24576 + off);
                MMA16816(oacc[nj * 2 + 0], ph, fvh[0], fvh[1]);
                MMA16816(oacc[nj * 2 + 1], ph, fvh[2], fvh[3]);
                MMA16816(oacc[nj * 2 + 0], pl, fvh[0], fvh[1]);
                MMA16816(oacc[nj * 2 + 1], pl, fvh[2], fvh[3]);
                MMA16816(oacc[nj * 2 + 0], ph, fvl[0], fvl[1]);
                MMA16816(oacc[nj * 2 + 1], ph, fvl[2], fvl[3]);
            }
        }
        __syncthreads();
    }

    // ---- epilogue: normalize, split hi/lo, write to g_ah/g_al ----
    const float inv0 = 1.f / l0, inv1 = 1.f / l1;
    const size_t r0off = ((size_t)b * Sc + qi0) * Dc + h * HDc;
    const size_t r1off = ((size_t)b * Sc + qi0 + 8) * Dc + h * HDc;
#pragma unroll
    for (int ni = 0; ni < 8; ni++) {
        const int col = ni * 8 + (lane & 3) * 2;
        u32 hv, lv;
        split_pack(oacc[ni][0] * inv0, oacc[ni][1] * inv0, hv, lv);
        *reinterpret_cast<u32*>(g_ah + r0off + col) = hv;
        *reinterpret_cast<u32*>(g_al + r0off + col) = lv;
        split_pack(oacc[ni][2] * inv1, oacc[ni][3] * inv1, hv, lv);
        *reinterpret_cast<u32*>(g_ah + r1off + col) = hv;
        *reinterpret_cast<u32*>(g_al + r1off + col) = lv;
    }
}

// ---------------------------------------------------------------------------
extern "C" void kernel_launch(void* const* d_in, const int* in_sizes, int n_in,
                              void* d_out, int out_size)
{
    const float* X     = (const float*)d_in[0];
    const float* W_qkv = (const float*)d_in[1];
    const float* b_qkv = (const float*)d_in[2];
    const float* W_out = (const float*)d_in[3];
    const float* b_out = (const float*)d_in[4];
    float* out = (float*)d_out;

    cudaFuncSetAttribute(gemm_mma<0>, cudaFuncAttributeMaxDynamicSharedMemorySize, GEMM_SMEM);
    cudaFuncSetAttribute(gemm_mma<1>, cudaFuncAttributeMaxDynamicSharedMemorySize, GEMM_SMEM);
    cudaFuncSetAttribute(attn_mma, cudaFuncAttributeMaxDynamicSharedMemorySize, ATT_SMEM);

    // bf16 splits
    split_rm<<<1024, 256>>>(X, Mtot * Dc / 4);
    split_tr<0><<<dim3(3 * Dc / 32, Dc / 32), dim3(32, 8)>>>(W_qkv, Dc, 3 * Dc);
    split_tr<1><<<dim3(Dc / 32, Dc / 32), dim3(32, 8)>>>(W_out, Dc, Dc);

    // 1) QKV projection -> bf16 hi/lo Q(scaled)/K/V in [bh,s,hd]
    gemm_mma<0><<<dim3(3 * Dc / 64, Mtot / 128), 256, GEMM_SMEM>>>(b_qkv, nullptr, 3 * Dc, Dc);

    // 2) causal flash attention (tensor cores) -> g_ah/g_al (hi/lo, [b,s,D])
    attn_mma<<<dim3(Sc / 128, Bc * Hc), 256, ATT_SMEM>>>();

    // 3) out-proj -> d_out
    gemm_mma<1><<<dim3(Dc / 64, Mtot / 128), 256, GEMM_SMEM>>>(b_out, out, Dc, Dc);
}

// round 9
// speedup vs baseline: 1.2523x; 1.2051x over previous
#include <cuda_runtime.h>
#include <cuda_bf16.h>
#include <cuda_fp16.h>
#include <math.h>
#include <stdint.h>

// Problem constants
#define Bc   2
#define Sc   2048
#define Dc   1024
#define Hc   16
#define HDc  64
#define Mtot 4096
#define SCALE 0.03125f          // 1/sqrt(1024)
#define NEGINF (-1e30f)

typedef unsigned long long u64;
typedef uint32_t u32;

// ---------------- scratch (device globals; referenced ONLY in device code) --
__device__ __half g_q16[(size_t)Bc * Hc * Sc * HDc];   // fp16, pre-scaled
__device__ __half g_k16[(size_t)Bc * Hc * Sc * HDc];   // fp16
__device__ __half g_vh16[(size_t)Bc * Hc * Sc * HDc];  // fp16 hi
__device__ __half g_vl16[(size_t)Bc * Hc * Sc * HDc];  // fp16 lo

__device__ __nv_bfloat16 g_ah[(size_t)Mtot * Dc];      // A hi (X, then attn out)
__device__ __nv_bfloat16 g_al[(size_t)Mtot * Dc];
__device__ __nv_bfloat16 g_wqh[(size_t)3 * Dc * Dc];   // W_qkv^T hi  [3072, 1024]
__device__ __nv_bfloat16 g_wql[(size_t)3 * Dc * Dc];
__device__ __nv_bfloat16 g_woh[(size_t)Dc * Dc];       // W_out^T hi  [1024, 1024]
__device__ __nv_bfloat16 g_wol[(size_t)Dc * Dc];

// ---------------- PTX helpers (non-arch-specific, sm_80 class) --------------
__device__ __forceinline__ u32 smem_u32_of(const void* p) {
    u32 a;
    asm("{ .reg .u64 t; cvta.to.shared.u64 t, %1; cvt.u32.u64 %0, t; }" : "=r"(a) : "l"(p));
    return a;
}
__device__ __forceinline__ void cp16(u32 dst, const void* src) {
    asm volatile("cp.async.cg.shared.global [%0], [%1], 16;" :: "r"(dst), "l"(src));
}
#define CP_COMMIT() asm volatile("cp.async.commit_group;" ::: "memory")
#define CP_WAIT1()  asm volatile("cp.async.wait_group 1;" ::: "memory")
#define CP_WAIT0()  asm volatile("cp.async.wait_group 0;" ::: "memory")

#define LDX4(r, addr) \
    asm volatile("ldmatrix.sync.aligned.m8n8.x4.shared.b16 {%0,%1,%2,%3}, [%4];" \
        : "=r"((r)[0]), "=r"((r)[1]), "=r"((r)[2]), "=r"((r)[3]) : "r"(addr))
#define LDX4T(r, addr) \
    asm volatile("ldmatrix.sync.aligned.m8n8.x4.trans.shared.b16 {%0,%1,%2,%3}, [%4];" \
        : "=r"((r)[0]), "=r"((r)[1]), "=r"((r)[2]), "=r"((r)[3]) : "r"(addr))

#define MMA16816(d, a, b0, b1) \
    asm volatile("mma.sync.aligned.m16n8k16.row.col.f32.bf16.bf16.f32 " \
        "{%0,%1,%2,%3}, {%4,%5,%6,%7}, {%8,%9}, {%0,%1,%2,%3};" \
        : "+f"((d)[0]), "+f"((d)[1]), "+f"((d)[2]), "+f"((d)[3]) \
        : "r"((a)[0]), "r"((a)[1]), "r"((a)[2]), "r"((a)[3]), "r"(b0), "r"(b1))

#define MMA16816H(d, a, b0, b1) \
    asm volatile("mma.sync.aligned.m16n8k16.row.col.f32.f16.f16.f32 " \
        "{%0,%1,%2,%3}, {%4,%5,%6,%7}, {%8,%9}, {%0,%1,%2,%3};" \
        : "+f"((d)[0]), "+f"((d)[1]), "+f"((d)[2]), "+f"((d)[3]) \
        : "r"((a)[0]), "r"((a)[1]), "r"((a)[2]), "r"((a)[3]), "r"(b0), "r"(b1))

// split v0,v1 (fp32) -> packed bf16x2 hi + lo residual
__device__ __forceinline__ void split_pack(float v0, float v1, u32& h, u32& l) {
    __nv_bfloat162 hb = __floats2bfloat162_rn(v0, v1);
    h = *reinterpret_cast<u32*>(&hb);
    float r0 = v0 - __low2float(hb);
    float r1 = v1 - __high2float(hb);
    __nv_bfloat162 lb = __floats2bfloat162_rn(r0, r1);
    l = *reinterpret_cast<u32*>(&lb);
}

// split v0,v1 (fp32) -> packed fp16x2 hi + lo residual
__device__ __forceinline__ void split_pack_h(float v0, float v1, u32& h, u32& l) {
    __half2 hb = __floats2half2_rn(v0, v1);
    h = *reinterpret_cast<u32*>(&hb);
    float r0 = v0 - __low2float(hb);
    float r1 = v1 - __high2float(hb);
    __half2 lb = __floats2half2_rn(r0, r1);
    l = *reinterpret_cast<u32*>(&lb);
}
__device__ __forceinline__ u32 pack_h2(float v0, float v1) {
    __half2 hb = __floats2half2_rn(v0, v1);
    return *reinterpret_cast<u32*>(&hb);
}

// ---------------------------------------------------------------------------
// Split kernels: fp32 -> (hi, lo) bf16
// ---------------------------------------------------------------------------
__global__ void split_rm(const float* __restrict__ src, int n4)
{
    __nv_bfloat16* hi = g_ah;
    __nv_bfloat16* lo = g_al;
    for (int i = blockIdx.x * blockDim.x + threadIdx.x; i < n4; i += gridDim.x * blockDim.x) {
        float4 v = reinterpret_cast<const float4*>(src)[i];
        uint2 hv, lv;
        split_pack(v.x, v.y, hv.x, lv.x);
        split_pack(v.z, v.w, hv.y, lv.y);
        reinterpret_cast<uint2*>(hi)[i] = hv;
        reinterpret_cast<uint2*>(lo)[i] = lv;
    }
}

// W [Kd, Nd] row-major -> hi/lo [Nd, Kd]. MODE 0 -> g_wqh/g_wql, MODE 1 -> g_woh/g_wol.
template <int MODE>
__global__ void split_tr(const float* __restrict__ W, int Kd, int Nd)
{
    __nv_bfloat16* hi = (MODE == 0) ? g_wqh : g_woh;
    __nv_bfloat16* lo = (MODE == 0) ? g_wql : g_wol;
    __shared__ float t[32][33];
    const int n0 = blockIdx.x * 32, k0 = blockIdx.y * 32;
    const int tx = threadIdx.x, ty = threadIdx.y;
#pragma unroll
    for (int i = 0; i < 4; i++)
        t[ty + i * 8][tx] = W[(size_t)(k0 + ty + i * 8) * Nd + n0 + tx];
    __syncthreads();
#pragma unroll
    for (int i = 0; i < 4; i++) {
        const int nn = ty + i * 8;
        float v = t[tx][nn];
        __nv_bfloat16 h = __float2bfloat16_rn(v);
        __nv_bfloat16 l = __float2bfloat16_rn(v - __bfloat162float(h));
        hi[(size_t)(n0 + nn) * Kd + k0 + tx] = h;
        lo[(size_t)(n0 + nn) * Kd + k0 + tx] = l;
    }
}

// ---------------------------------------------------------------------------
// mma.sync bf16-split GEMM, 2 CTAs/SM. Tile 128x64, 8 warps (4x2), warp 32x32.
// MODE 0: epilogue -> fp16 Q(scaled)/K single, V hi/lo.  MODE 1: fp32 + bias -> C.
// ---------------------------------------------------------------------------
#define KC        64
#define OFF_AH    0
#define OFF_AL    16384
#define OFF_BH    32768
#define OFF_BL    40960
#define STAGE_B   49152          // 48 KB
#define GEMM_SMEM (2 * STAGE_B)  // 96 KB -> 2 CTAs/SM

__device__ __forceinline__ void load_chunk(u32 stg,
    const __nv_bfloat16* __restrict__ Ah, const __nv_bfloat16* __restrict__ Al,
    const __nv_bfloat16* __restrict__ Bh, const __nv_bfloat16* __restrict__ Bl,
    int bm, int bn, int col0, int K, int tid)
{
#pragma unroll
    for (int i = 0; i < 8; i++) {
        const int idx = i * 256 + tid;
        const int hl = idx >> 10;
        const int r = (idx >> 3) & 127;
        const int cc = idx & 7;
        u32 off = (u32)((r << 7) + (cc << 4));
        off ^= (off >> 3) & 0x70;
        const __nv_bfloat16* s = hl ? Al : Ah;
        cp16(stg + (hl ? OFF_AL : OFF_AH) + off, s + (size_t)(bm + r) * K + col0 + cc * 8);
    }
#pragma unroll
    for (int i = 0; i < 4; i++) {
        const int idx = i * 256 + tid;
        const int hl = i >> 1;
        const int r = (idx >> 3) & 63;
        const int cc = idx & 7;
        u32 off = (u32)((r << 7) + (cc << 4));
        off ^= (off >> 3) & 0x70;
        const __nv_bfloat16* s = hl ? Bl : Bh;
        cp16(stg + (hl ? OFF_BL : OFF_BH) + off, s + (size_t)(bn + r) * K + col0 + cc * 8);
    }
}

template <int MODE>
__global__ __launch_bounds__(256, 2)
void gemm_mma(const float* __restrict__ bias, float* __restrict__ C, int N, int K)
{
    const __nv_bfloat16* Ah = g_ah;
    const __nv_bfloat16* Al = g_al;
    const __nv_bfloat16* Bh = (MODE == 0) ? g_wqh : g_woh;
    const __nv_bfloat16* Bl = (MODE == 0) ? g_wql : g_wol;

    extern __shared__ char smem[];
    const u32 sbase = smem_u32_of(smem);
    const int tid = threadIdx.x;
    const int bm = blockIdx.y * 128;
    const int bn = blockIdx.x * 64;
    const int lane = tid & 31, warp = tid >> 5;
    const int m0w = (warp >> 1) * 32;
    const int n0w = (warp & 1) * 32;

    float acc[2][4][4];
#pragma unroll
    for (int mi = 0; mi < 2; mi++)
#pragma unroll
        for (int ni = 0; ni < 4; ni++)
#pragma unroll
            for (int q = 0; q < 4; q++) acc[mi][ni][q] = 0.f;

    const int aRowOff = lane & 15;
    const u32 aKb = (u32)((lane >> 4) << 4);
    const int bRowOff = ((lane >> 4) & 1) * 8 + (lane & 7);
    const u32 bKb = (u32)(((lane >> 3) & 1) << 4);

    const int NC = K / KC;

    load_chunk(sbase, Ah, Al, Bh, Bl, bm, bn, 0, K, tid);
    CP_COMMIT();

    for (int c = 0; c < NC; c++) {
        const u32 stg = sbase + (u32)(c & 1) * STAGE_B;
        if (c + 1 < NC) {
            load_chunk(sbase + (u32)((c + 1) & 1) * STAGE_B, Ah, Al, Bh, Bl, bm, bn, (c + 1) * KC, K, tid);
            CP_COMMIT();
            CP_WAIT1();
        } else {
            CP_WAIT0();
        }
        __syncthreads();

#pragma unroll
        for (int k16 = 0; k16 < 4; k16++) {
            u32 fAh[2][4], fAl[2][4];
#pragma unroll
            for (int mi = 0; mi < 2; mi++) {
                u32 off = (u32)(m0w + mi * 16 + aRowOff) * 128 + aKb + (u32)k16 * 32;
                off ^= (off >> 3) & 0x70;
                LDX4(fAh[mi], stg + OFF_AH + off);
                LDX4(fAl[mi], stg + OFF_AL + off);
            }
            u32 fBh[2][4], fBl[2][4];
#pragma unroll
            for (int bi = 0; bi < 2; bi++) {
                u32 off = (u32)(n0w + bi * 16 + bRowOff) * 128 + bKb + (u32)k16 * 32;
                off ^= (off >> 3) & 0x70;
                LDX4(fBh[bi], stg + OFF_BH + off);
                LDX4(fBl[bi], stg + OFF_BL + off);
            }
#pragma unroll
            for (int mi = 0; mi < 2; mi++)
#pragma unroll
                for (int ni = 0; ni < 4; ni++)
                    MMA16816(acc[mi][ni], fAh[mi],
                             fBh[ni >> 1][(ni & 1) * 2], fBh[ni >> 1][(ni & 1) * 2 + 1]);
#pragma unroll
            for (int mi = 0; mi < 2; mi++)
#pragma unroll
                for (int ni = 0; ni < 4; ni++)
                    MMA16816(acc[mi][ni], fAh[mi],
                             fBl[ni >> 1][(ni & 1) * 2], fBl[ni >> 1][(ni & 1) * 2 + 1]);
#pragma unroll
            for (int mi = 0; mi < 2; mi++)
#pragma unroll
                for (int ni = 0; ni < 4; ni++)
                    MMA16816(acc[mi][ni], fAl[mi],
                             fBh[ni >> 1][(ni & 1) * 2], fBh[ni >> 1][(ni & 1) * 2 + 1]);
        }
        __syncthreads();
    }

#pragma unroll
    for (int ni = 0; ni < 4; ni++) {
        const int g = bn + n0w + ni * 8 + (lane & 3) * 2;
        const float bv0 = bias[g], bv1 = bias[g + 1];
        if (MODE == 1) {
#pragma unroll
            for (int mi = 0; mi < 2; mi++) {
                const int r0 = bm + m0w + mi * 16 + (lane >> 2);
                float2 v0 = {acc[mi][ni][0] + bv0, acc[mi][ni][1] + bv1};
                float2 v1 = {acc[mi][ni][2] + bv0, acc[mi][ni][3] + bv1};
                *reinterpret_cast<float2*>(C + (size_t)r0 * N + g) = v0;
                *reinterpret_cast<float2*>(C + (size_t)(r0 + 8) * N + g) = v1;
            }
        } else {
            const int qkv = g >> 10;
            const int h = (g & 1023) >> 6;
            const int c0 = g & 63;
#pragma unroll
            for (int mi = 0; mi < 2; mi++) {
#pragma unroll
                for (int half = 0; half < 2; half++) {
                    const int row = bm + m0w + mi * 16 + (lane >> 2) + half * 8;
                    const int b = row >> 11;
                    const int sI = row & (Sc - 1);
                    const float v0 = acc[mi][ni][half * 2 + 0] + bv0;
                    const float v1 = acc[mi][ni][half * 2 + 1] + bv1;
                    const size_t o = (((size_t)(b * Hc + h)) * Sc + sI) * HDc + c0;
                    if (qkv == 0) {
                        *reinterpret_cast<u32*>(g_q16 + o) = pack_h2(v0 * SCALE, v1 * SCALE);
                    } else if (qkv == 1) {
                        *reinterpret_cast<u32*>(g_k16 + o) = pack_h2(v0, v1);
                    } else {
                        u32 hv, lv;
                        split_pack_h(v0, v1, hv, lv);
                        *reinterpret_cast<u32*>(g_vh16 + o) = hv;
                        *reinterpret_cast<u32*>(g_vl16 + o) = lv;
                    }
                }
            }
        }
    }
}

// ---------------------------------------------------------------------------
// FlashAttention-2 with fp16 mma.sync: QK single-product, PV 2-product.
// CTA = 128 queries, 8 warps (16 rows each). Key tiles of 64.
// ---------------------------------------------------------------------------
#define A_Q    0                 // 16 KB: Q fp16, 128 x 64
#define A_STG  16384             // 2 stages x 24576: {K 8192, VH 8192, VL 8192}
#define STG_SZ 24576
#define ATT_SMEM (16384 + 2 * STG_SZ)   // 64 KB -> 2 CTAs/SM

__device__ __forceinline__ void attn_load_stage(u32 stg,
    const __half* Kk, const __half* Vh, const __half* Vl, int kt, int tid)
{
    // 1536 vec16: tile 0 = K, 1 = VH, 2 = VL (each 64 rows x 64 fp16 = 8 KB)
#pragma unroll
    for (int i = 0; i < 6; i++) {
        const int idx = i * 256 + tid;
        const int tile = idx >> 9;          // constant per i
        const int r = (idx >> 3) & 63;
        const int cc = idx & 7;
        u32 off = (u32)(r * 128 + cc * 16);
        off ^= (off >> 3) & 0x70;
        const __half* s = (tile == 0) ? Kk : ((tile == 1) ? Vh : Vl);
        cp16(stg + (u32)tile * 8192 + off, s + (size_t)(kt * 64 + r) * HDc + cc * 8);
    }
}

__global__ __launch_bounds__(256, 2)
void attn_mma()
{
    const int bh = blockIdx.y;
    const int qb = (int)gridDim.x - 1 - (int)blockIdx.x;   // big tiles first
    const int b = bh >> 4, h = bh & 15;

    extern __shared__ char smem[];
    const u32 sb = smem_u32_of(smem);
    const int tid = threadIdx.x, lane = tid & 31, warp = tid >> 5;
    const int m0w = warp * 16;

    const size_t bhoff = (size_t)bh * Sc * HDc;
    const __half* Qq = g_q16 + bhoff;
    const __half* Kk = g_k16 + bhoff;
    const __half* Vh = g_vh16 + bhoff;
    const __half* Vl = g_vl16 + bhoff;

    const int NT = 2 * qb + 2;

    // preload Q tile (fp16, 1024 vec16) + stage 0
#pragma unroll
    for (int i = 0; i < 4; i++) {
        const int idx = i * 256 + tid;
        const int r = (idx >> 3) & 127;
        const int cc = idx & 7;
        u32 off = (u32)(r * 128 + cc * 16);
        off ^= (off >> 3) & 0x70;
        cp16(sb + A_Q + off, Qq + (size_t)(qb * 128 + r) * HDc + cc * 8);
    }
    attn_load_stage(sb + A_STG, Kk, Vh, Vl, 0, tid);
    CP_COMMIT();

    const int aRowOff = lane & 15;
    const u32 aKb = (u32)((lane >> 4) << 4);
    const int bRowOff = ((lane >> 4) & 1) * 8 + (lane & 7);
    const u32 bKb = (u32)(((lane >> 3) & 1) << 4);

    float oacc[8][4];
#pragma unroll
    for (int ni = 0; ni < 8; ni++)
#pragma unroll
        for (int q = 0; q < 4; q++) oacc[ni][q] = 0.f;
    float m0 = NEGINF, m1 = NEGINF, l0 = 0.f, l1 = 0.f;

    const int qi0 = qb * 128 + m0w + (lane >> 2);

    for (int c = 0; c < NT; c++) {
        const u32 stg = sb + A_STG + (u32)(c & 1) * STG_SZ;
        if (c + 1 < NT) {
            attn_load_stage(sb + A_STG + (u32)((c + 1) & 1) * STG_SZ, Kk, Vh, Vl, c + 1, tid);
            CP_COMMIT();
            CP_WAIT1();
        } else {
            CP_WAIT0();
        }
        __syncthreads();

        // ---- S = Q K^T (single product, fp16) ----
        float sacc[8][4];
#pragma unroll
        for (int ni = 0; ni < 8; ni++)
#pragma unroll
            for (int q = 0; q < 4; q++) sacc[ni][q] = 0.f;

#pragma unroll
        for (int kk = 0; kk < 4; kk++) {
            u32 qf[4];
            {
                u32 off = (u32)(m0w + aRowOff) * 128 + aKb + (u32)kk * 32;
                off ^= (off >> 3) & 0x70;
                LDX4(qf, sb + A_Q + off);
            }
            u32 fk[4][4];
#pragma unroll
            for (int g = 0; g < 4; g++) {
                u32 off = (u32)(g * 16 + bRowOff) * 128 + bKb + (u32)kk * 32;
                off ^= (off >> 3) & 0x70;
                LDX4(fk[g], stg + 0 + off);
            }
#pragma unroll
            for (int ni = 0; ni < 8; ni++)
                MMA16816H(sacc[ni], qf,
                          fk[ni >> 1][(ni & 1) * 2], fk[ni >> 1][(ni & 1) * 2 + 1]);
        }

        // ---- causal mask (only last two tiles) ----
        if (c >= 2 * qb) {
#pragma unroll
            for (int ni = 0; ni < 8; ni++) {
                const int col = c * 64 + ni * 8 + (lane & 3) * 2;
                if (col > qi0)     sacc[ni][0] = NEGINF;
                if (col + 1 > qi0) sacc[ni][1] = NEGINF;
                if (col > qi0 + 8)     sacc[ni][2] = NEGINF;
                if (col + 1 > qi0 + 8) sacc[ni][3] = NEGINF;
            }
        }

        // ---- online softmax ----
        float mx0 = NEGINF, mx1 = NEGINF;
#pragma unroll
        for (int ni = 0; ni < 8; ni++) {
            mx0 = fmaxf(mx0, fmaxf(sacc[ni][0], sacc[ni][1]));
            mx1 = fmaxf(mx1, fmaxf(sacc[ni][2], sacc[ni][3]));
        }
        mx0 = fmaxf(mx0, __shfl_xor_sync(0xffffffffu, mx0, 1));
        mx0 = fmaxf(mx0, __shfl_xor_sync(0xffffffffu, mx0, 2));
        mx1 = fmaxf(mx1, __shfl_xor_sync(0xffffffffu, mx1, 1));
        mx1 = fmaxf(mx1, __shfl_xor_sync(0xffffffffu, mx1, 2));

        const float nm0 = fmaxf(m0, mx0), nm1 = fmaxf(m1, mx1);
        const float cr0 = __expf(m0 - nm0), cr1 = __expf(m1 - nm1);
        m0 = nm0; m1 = nm1;

        float s0 = 0.f, s1 = 0.f;
#pragma unroll
        for (int ni = 0; ni < 8; ni++) {
            sacc[ni][0] = __expf(sacc[ni][0] - nm0);
            sacc[ni][1] = __expf(sacc[ni][1] - nm0);
            sacc[ni][2] = __expf(sacc[ni][2] - nm1);
            sacc[ni][3] = __expf(sacc[ni][3] - nm1);
            s0 += sacc[ni][0] + sacc[ni][1];
            s1 += sacc[ni][2] + sacc[ni][3];
        }
        s0 += __shfl_xor_sync(0xffffffffu, s0, 1);
        s0 += __shfl_xor_sync(0xffffffffu, s0, 2);
        s1 += __shfl_xor_sync(0xffffffffu, s1, 1);
        s1 += __shfl_xor_sync(0xffffffffu, s1, 2);
        l0 = l0 * cr0 + s0;
        l1 = l1 * cr1 + s1;

#pragma unroll
        for (int ni = 0; ni < 8; ni++) {
            oacc[ni][0] *= cr0; oacc[ni][1] *= cr0;
            oacc[ni][2] *= cr1; oacc[ni][3] *= cr1;
        }

        // ---- O += P V (P single fp16, V hi+lo: 2 products) ----
#pragma unroll
        for (int kk = 0; kk < 4; kk++) {
            u32 ph[4];
            ph[0] = pack_h2(sacc[2 * kk][0],     sacc[2 * kk][1]);
            ph[1] = pack_h2(sacc[2 * kk][2],     sacc[2 * kk][3]);
            ph[2] = pack_h2(sacc[2 * kk + 1][0], sacc[2 * kk + 1][1]);
            ph[3] = pack_h2(sacc[2 * kk + 1][2], sacc[2 * kk + 1][3]);
#pragma unroll
            for (int nj = 0; nj < 4; nj++) {
                u32 fvh[4], fvl[4];
                u32 off = (u32)(kk * 16 + (lane & 15)) * 128 + (u32)nj * 32 + (u32)((lane >> 4) << 4);
                off ^= (off >> 3) & 0x70;
                LDX4T(fvh, stg + 8192 + off);
                LDX4T(fvl, stg + 16384 + off);
                MMA16816H(oacc[nj * 2 + 0], ph, fvh[0], fvh[1]);
                MMA16816H(oacc[nj * 2 + 1], ph, fvh[2], fvh[3]);
                MMA16816H(oacc[nj * 2 + 0], ph, fvl[0], fvl[1]);
                MMA16816H(oacc[nj * 2 + 1], ph, fvl[2], fvl[3]);
            }
        }
        __syncthreads();
    }

    // ---- epilogue: normalize, split hi/lo bf16, write to g_ah/g_al ----
    const float inv0 = 1.f / l0, inv1 = 1.f / l1;
    const size_t r0off = ((size_t)b * Sc + qi0) * Dc + h * HDc;
    const size_t r1off = ((size_t)b * Sc + qi0 + 8) * Dc + h * HDc;
#pragma unroll
    for (int ni = 0; ni < 8; ni++) {
        const int col = ni * 8 + (lane & 3) * 2;
        u32 hv, lv;
        split_pack(oacc[ni][0] * inv0, oacc[ni][1] * inv0, hv, lv);
        *reinterpret_cast<u32*>(g_ah + r0off + col) = hv;
        *reinterpret_cast<u32*>(g_al + r0off + col) = lv;
        split_pack(oacc[ni][2] * inv1, oacc[ni][3] * inv1, hv, lv);
        *reinterpret_cast<u32*>(g_ah + r1off + col) = hv;
        *reinterpret_cast<u32*>(g_al + r1off + col) = lv;
    }
}

// ---------------------------------------------------------------------------
extern "C" void kernel_launch(void* const* d_in, const int* in_sizes, int n_in,
                              void* d_out, int out_size)
{
    const float* X     = (const float*)d_in[0];
    const float* W_qkv = (const float*)d_in[1];
    const float* b_qkv = (const float*)d_in[2];
    const float* W_out = (const float*)d_in[3];
    const float* b_out = (const float*)d_in[4];
    float* out = (float*)d_out;

    cudaFuncSetAttribute(gemm_mma<0>, cudaFuncAttributeMaxDynamicSharedMemorySize, GEMM_SMEM);
    cudaFuncSetAttribute(gemm_mma<1>, cudaFuncAttributeMaxDynamicSharedMemorySize, GEMM_SMEM);
    cudaFuncSetAttribute(attn_mma, cudaFuncAttributeMaxDynamicSharedMemorySize, ATT_SMEM);

    // bf16 splits
    split_rm<<<1024, 256>>>(X, Mtot * Dc / 4);
    split_tr<0><<<dim3(3 * Dc / 32, Dc / 32), dim3(32, 8)>>>(W_qkv, Dc, 3 * Dc);
    split_tr<1><<<dim3(Dc / 32, Dc / 32), dim3(32, 8)>>>(W_out, Dc, Dc);

    // 1) QKV projection -> fp16 Q(scaled)/K single, V hi/lo in [bh,s,hd]
    gemm_mma<0><<<dim3(3 * Dc / 64, Mtot / 128), 256, GEMM_SMEM>>>(b_qkv, nullptr, 3 * Dc, Dc);

    // 2) causal flash attention (fp16 tensor cores) -> g_ah/g_al (hi/lo, [b,s,D])
    attn_mma<<<dim3(Sc / 128, Bc * Hc), 256, ATT_SMEM>>>();

    // 3) out-proj -> d_out
    gemm_mma<1><<<dim3(Dc / 64, Mtot / 128), 256, GEMM_SMEM>>>(b_out, out, Dc, Dc);
}

// round 10
// speedup vs baseline: 1.5098x; 1.2056x over previous
#include <cuda_runtime.h>
#include <cuda_bf16.h>
#include <cuda_fp16.h>
#include <math.h>
#include <stdint.h>

// Problem constants
#define Bc   2
#define Sc   2048
#define Dc   1024
#define Hc   16
#define HDc  64
#define Mtot 4096
#define SCALE 0.03125f          // 1/sqrt(1024)
#define NEGINF (-1e30f)

typedef unsigned long long u64;
typedef uint32_t u32;

// ---------------- scratch (device globals; referenced ONLY in device code) --
__device__ __half g_q16[(size_t)Bc * Hc * Sc * HDc];   // fp16, pre-scaled
__device__ __half g_k16[(size_t)Bc * Hc * Sc * HDc];   // fp16
__device__ __half g_vh16[(size_t)Bc * Hc * Sc * HDc];  // fp16 hi
__device__ __half g_vl16[(size_t)Bc * Hc * Sc * HDc];  // fp16 lo

__device__ __half g_ah[(size_t)Mtot * Dc];             // A hi fp16 (X, then attn out)
__device__ __half g_al[(size_t)Mtot * Dc];             // A lo fp16
__device__ __half g_wq16[(size_t)3 * Dc * Dc];         // W_qkv^T fp16  [3072, 1024]
__device__ __half g_wo16[(size_t)Dc * Dc];             // W_out^T fp16  [1024, 1024]

// ---------------- PTX helpers (non-arch-specific, sm_80 class) --------------
__device__ __forceinline__ u32 smem_u32_of(const void* p) {
    u32 a;
    asm("{ .reg .u64 t; cvta.to.shared.u64 t, %1; cvt.u32.u64 %0, t; }" : "=r"(a) : "l"(p));
    return a;
}
__device__ __forceinline__ void cp16(u32 dst, const void* src) {
    asm volatile("cp.async.cg.shared.global [%0], [%1], 16;" :: "r"(dst), "l"(src));
}
#define CP_COMMIT() asm volatile("cp.async.commit_group;" ::: "memory")
#define CP_WAIT1()  asm volatile("cp.async.wait_group 1;" ::: "memory")
#define CP_WAIT0()  asm volatile("cp.async.wait_group 0;" ::: "memory")

#define LDX4(r, addr) \
    asm volatile("ldmatrix.sync.aligned.m8n8.x4.shared.b16 {%0,%1,%2,%3}, [%4];" \
        : "=r"((r)[0]), "=r"((r)[1]), "=r"((r)[2]), "=r"((r)[3]) : "r"(addr))
#define LDX4T(r, addr) \
    asm volatile("ldmatrix.sync.aligned.m8n8.x4.trans.shared.b16 {%0,%1,%2,%3}, [%4];" \
        : "=r"((r)[0]), "=r"((r)[1]), "=r"((r)[2]), "=r"((r)[3]) : "r"(addr))

#define MMA16816H(d, a, b0, b1) \
    asm volatile("mma.sync.aligned.m16n8k16.row.col.f32.f16.f16.f32 " \
        "{%0,%1,%2,%3}, {%4,%5,%6,%7}, {%8,%9}, {%0,%1,%2,%3};" \
        : "+f"((d)[0]), "+f"((d)[1]), "+f"((d)[2]), "+f"((d)[3]) \
        : "r"((a)[0]), "r"((a)[1]), "r"((a)[2]), "r"((a)[3]), "r"(b0), "r"(b1))

// split v0,v1 (fp32) -> packed fp16x2 hi + lo residual
__device__ __forceinline__ void split_pack_h(float v0, float v1, u32& h, u32& l) {
    __half2 hb = __floats2half2_rn(v0, v1);
    h = *reinterpret_cast<u32*>(&hb);
    float r0 = v0 - __low2float(hb);
    float r1 = v1 - __high2float(hb);
    __half2 lb = __floats2half2_rn(r0, r1);
    l = *reinterpret_cast<u32*>(&lb);
}
__device__ __forceinline__ u32 pack_h2(float v0, float v1) {
    __half2 hb = __floats2half2_rn(v0, v1);
    return *reinterpret_cast<u32*>(&hb);
}

// ---------------------------------------------------------------------------
// Split kernels
// ---------------------------------------------------------------------------
// fp32 -> fp16 hi/lo into g_ah/g_al
__global__ void split_rm(const float* __restrict__ src, int n4)
{
    for (int i = blockIdx.x * blockDim.x + threadIdx.x; i < n4; i += gridDim.x * blockDim.x) {
        float4 v = reinterpret_cast<const float4*>(src)[i];
        uint2 hv, lv;
        split_pack_h(v.x, v.y, hv.x, lv.x);
        split_pack_h(v.z, v.w, hv.y, lv.y);
        reinterpret_cast<uint2*>(g_ah)[i] = hv;
        reinterpret_cast<uint2*>(g_al)[i] = lv;
    }
}

// W [Kd, Nd] row-major -> single fp16 [Nd, Kd]. MODE 0 -> g_wq16, MODE 1 -> g_wo16.
template <int MODE>
__global__ void split_tr(const float* __restrict__ W, int Kd, int Nd)
{
    __half* dst = (MODE == 0) ? g_wq16 : g_wo16;
    __shared__ float t[32][33];
    const int n0 = blockIdx.x * 32, k0 = blockIdx.y * 32;
    const int tx = threadIdx.x, ty = threadIdx.y;
#pragma unroll
    for (int i = 0; i < 4; i++)
        t[ty + i * 8][tx] = W[(size_t)(k0 + ty + i * 8) * Nd + n0 + tx];
    __syncthreads();
#pragma unroll
    for (int i = 0; i < 4; i++) {
        const int nn = ty + i * 8;
        dst[(size_t)(n0 + nn) * Kd + k0 + tx] = __float2half_rn(t[tx][nn]);
    }
}

// ---------------------------------------------------------------------------
// mma.sync fp16 2-product GEMM, 2 CTAs/SM. Tile 128x64, 8 warps, warp 32x32.
// C = (Ah + Al) @ B^T + bias, all fp16 operands, fp32 accum.
// MODE 0: epilogue -> fp16 Q(scaled)/K single, V hi/lo.  MODE 1: fp32 + bias -> C.
// ---------------------------------------------------------------------------
#define KC        64
#define OFF_AH    0
#define OFF_AL    16384
#define OFF_B     32768
#define STAGE_B   40960          // 40 KB
#define GEMM_SMEM (2 * STAGE_B)  // 80 KB -> 2 CTAs/SM

__device__ __forceinline__ void load_chunk(u32 stg,
    const __half* __restrict__ Ah, const __half* __restrict__ Al,
    const __half* __restrict__ Bw,
    int bm, int bn, int col0, int K, int tid)
{
    // A: 128 rows x 64 fp16 x2 (hi+lo) = 2048 vec16
#pragma unroll
    for (int i = 0; i < 8; i++) {
        const int idx = i * 256 + tid;
        const int hl = idx >> 10;            // constant per i
        const int r = (idx >> 3) & 127;
        const int cc = idx & 7;
        u32 off = (u32)((r << 7) + (cc << 4));
        off ^= (off >> 3) & 0x70;
        const __half* s = hl ? Al : Ah;
        cp16(stg + (hl ? OFF_AL : OFF_AH) + off, s + (size_t)(bm + r) * K + col0 + cc * 8);
    }
    // B: 64 rows x 64 fp16 = 512 vec16
#pragma unroll
    for (int i = 0; i < 2; i++) {
        const int idx = i * 256 + tid;
        const int r = (idx >> 3) & 63;
        const int cc = idx & 7;
        u32 off = (u32)((r << 7) + (cc << 4));
        off ^= (off >> 3) & 0x70;
        cp16(stg + OFF_B + off, Bw + (size_t)(bn + r) * K + col0 + cc * 8);
    }
}

template <int MODE>
__global__ __launch_bounds__(256, 2)
void gemm_mma(const float* __restrict__ bias, float* __restrict__ C, int N, int K)
{
    const __half* Ah = g_ah;
    const __half* Al = g_al;
    const __half* Bw = (MODE == 0) ? g_wq16 : g_wo16;

    extern __shared__ char smem[];
    const u32 sbase = smem_u32_of(smem);
    const int tid = threadIdx.x;
    const int bm = blockIdx.y * 128;
    const int bn = blockIdx.x * 64;
    const int lane = tid & 31, warp = tid >> 5;
    const int m0w = (warp >> 1) * 32;
    const int n0w = (warp & 1) * 32;

    float acc[2][4][4];
#pragma unroll
    for (int mi = 0; mi < 2; mi++)
#pragma unroll
        for (int ni = 0; ni < 4; ni++)
#pragma unroll
            for (int q = 0; q < 4; q++) acc[mi][ni][q] = 0.f;

    const int aRowOff = lane & 15;
    const u32 aKb = (u32)((lane >> 4) << 4);
    const int bRowOff = ((lane >> 4) & 1) * 8 + (lane & 7);
    const u32 bKb = (u32)(((lane >> 3) & 1) << 4);

    const int NC = K / KC;

    load_chunk(sbase, Ah, Al, Bw, bm, bn, 0, K, tid);
    CP_COMMIT();

    for (int c = 0; c < NC; c++) {
        const u32 stg = sbase + (u32)(c & 1) * STAGE_B;
        if (c + 1 < NC) {
            load_chunk(sbase + (u32)((c + 1) & 1) * STAGE_B, Ah, Al, Bw, bm, bn, (c + 1) * KC, K, tid);
            CP_COMMIT();
            CP_WAIT1();
        } else {
            CP_WAIT0();
        }
        __syncthreads();

#pragma unroll
        for (int k16 = 0; k16 < 4; k16++) {
            u32 fAh[2][4], fAl[2][4];
#pragma unroll
            for (int mi = 0; mi < 2; mi++) {
                u32 off = (u32)(m0w + mi * 16 + aRowOff) * 128 + aKb + (u32)k16 * 32;
                off ^= (off >> 3) & 0x70;
                LDX4(fAh[mi], stg + OFF_AH + off);
                LDX4(fAl[mi], stg + OFF_AL + off);
            }
            u32 fB[2][4];
#pragma unroll
            for (int bi = 0; bi < 2; bi++) {
                u32 off = (u32)(n0w + bi * 16 + bRowOff) * 128 + bKb + (u32)k16 * 32;
                off ^= (off >> 3) & 0x70;
                LDX4(fB[bi], stg + OFF_B + off);
            }
#pragma unroll
            for (int mi = 0; mi < 2; mi++)
#pragma unroll
                for (int ni = 0; ni < 4; ni++)
                    MMA16816H(acc[mi][ni], fAh[mi],
                              fB[ni >> 1][(ni & 1) * 2], fB[ni >> 1][(ni & 1) * 2 + 1]);
#pragma unroll
            for (int mi = 0; mi < 2; mi++)
#pragma unroll
                for (int ni = 0; ni < 4; ni++)
                    MMA16816H(acc[mi][ni], fAl[mi],
                              fB[ni >> 1][(ni & 1) * 2], fB[ni >> 1][(ni & 1) * 2 + 1]);
        }
        __syncthreads();
    }

#pragma unroll
    for (int ni = 0; ni < 4; ni++) {
        const int g = bn + n0w + ni * 8 + (lane & 3) * 2;
        const float bv0 = bias[g], bv1 = bias[g + 1];
        if (MODE == 1) {
#pragma unroll
            for (int mi = 0; mi < 2; mi++) {
                const int r0 = bm + m0w + mi * 16 + (lane >> 2);
                float2 v0 = {acc[mi][ni][0] + bv0, acc[mi][ni][1] + bv1};
                float2 v1 = {acc[mi][ni][2] + bv0, acc[mi][ni][3] + bv1};
                *reinterpret_cast<float2*>(C + (size_t)r0 * N + g) = v0;
                *reinterpret_cast<float2*>(C + (size_t)(r0 + 8) * N + g) = v1;
            }
        } else {
            const int qkv = g >> 10;
            const int h = (g & 1023) >> 6;
            const int c0 = g & 63;
#pragma unroll
            for (int mi = 0; mi < 2; mi++) {
#pragma unroll
                for (int half = 0; half < 2; half++) {
                    const int row = bm + m0w + mi * 16 + (lane >> 2) + half * 8;
                    const int b = row >> 11;
                    const int sI = row & (Sc - 1);
                    const float v0 = acc[mi][ni][half * 2 + 0] + bv0;
                    const float v1 = acc[mi][ni][half * 2 + 1] + bv1;
                    const size_t o = (((size_t)(b * Hc + h)) * Sc + sI) * HDc + c0;
                    if (qkv == 0) {
                        *reinterpret_cast<u32*>(g_q16 + o) = pack_h2(v0 * SCALE, v1 * SCALE);
                    } else if (qkv == 1) {
                        *reinterpret_cast<u32*>(g_k16 + o) = pack_h2(v0, v1);
                    } else {
                        u32 hv, lv;
                        split_pack_h(v0, v1, hv, lv);
                        *reinterpret_cast<u32*>(g_vh16 + o) = hv;
                        *reinterpret_cast<u32*>(g_vl16 + o) = lv;
                    }
                }
            }
        }
    }
}

// ---------------------------------------------------------------------------
// FlashAttention-2 with fp16 mma.sync: QK single-product, PV 2-product.
// CTA = 128 queries, 8 warps (16 rows each). Key tiles of 64.
// ---------------------------------------------------------------------------
#define A_Q    0                 // 16 KB: Q fp16, 128 x 64
#define A_STG  16384             // 2 stages x 24576: {K 8192, VH 8192, VL 8192}
#define STG_SZ 24576
#define ATT_SMEM (16384 + 2 * STG_SZ)   // 64 KB -> 2 CTAs/SM

__device__ __forceinline__ void attn_load_stage(u32 stg,
    const __half* Kk, const __half* Vh, const __half* Vl, int kt, int tid)
{
#pragma unroll
    for (int i = 0; i < 6; i++) {
        const int idx = i * 256 + tid;
        const int tile = idx >> 9;
        const int r = (idx >> 3) & 63;
        const int cc = idx & 7;
        u32 off = (u32)(r * 128 + cc * 16);
        off ^= (off >> 3) & 0x70;
        const __half* s = (tile == 0) ? Kk : ((tile == 1) ? Vh : Vl);
        cp16(stg + (u32)tile * 8192 + off, s + (size_t)(kt * 64 + r) * HDc + cc * 8);
    }
}

__global__ __launch_bounds__(256, 2)
void attn_mma()
{
    const int bh = blockIdx.y;
    const int qb = (int)gridDim.x - 1 - (int)blockIdx.x;   // big tiles first
    const int b = bh >> 4, h = bh & 15;

    extern __shared__ char smem[];
    const u32 sb = smem_u32_of(smem);
    const int tid = threadIdx.x, lane = tid & 31, warp = tid >> 5;
    const int m0w = warp * 16;

    const size_t bhoff = (size_t)bh * Sc * HDc;
    const __half* Qq = g_q16 + bhoff;
    const __half* Kk = g_k16 + bhoff;
    const __half* Vh = g_vh16 + bhoff;
    const __half* Vl = g_vl16 + bhoff;

    const int NT = 2 * qb + 2;

    // preload Q tile + stage 0
#pragma unroll
    for (int i = 0; i < 4; i++) {
        const int idx = i * 256 + tid;
        const int r = (idx >> 3) & 127;
        const int cc = idx & 7;
        u32 off = (u32)(r * 128 + cc * 16);
        off ^= (off >> 3) & 0x70;
        cp16(sb + A_Q + off, Qq + (size_t)(qb * 128 + r) * HDc + cc * 8);
    }
    attn_load_stage(sb + A_STG, Kk, Vh, Vl, 0, tid);
    CP_COMMIT();

    const int aRowOff = lane & 15;
    const u32 aKb = (u32)((lane >> 4) << 4);
    const int bRowOff = ((lane >> 4) & 1) * 8 + (lane & 7);
    const u32 bKb = (u32)(((lane >> 3) & 1) << 4);

    float oacc[8][4];
#pragma unroll
    for (int ni = 0; ni < 8; ni++)
#pragma unroll
        for (int q = 0; q < 4; q++) oacc[ni][q] = 0.f;
    float m0 = NEGINF, m1 = NEGINF, l0 = 0.f, l1 = 0.f;

    const int qi0 = qb * 128 + m0w + (lane >> 2);

    for (int c = 0; c < NT; c++) {
        const u32 stg = sb + A_STG + (u32)(c & 1) * STG_SZ;
        if (c + 1 < NT) {
            attn_load_stage(sb + A_STG + (u32)((c + 1) & 1) * STG_SZ, Kk, Vh, Vl, c + 1, tid);
            CP_COMMIT();
            CP_WAIT1();
        } else {
            CP_WAIT0();
        }
        __syncthreads();

        // ---- S = Q K^T (single product, fp16) ----
        float sacc[8][4];
#pragma unroll
        for (int ni = 0; ni < 8; ni++)
#pragma unroll
            for (int q = 0; q < 4; q++) sacc[ni][q] = 0.f;

#pragma unroll
        for (int kk = 0; kk < 4; kk++) {
            u32 qf[4];
            {
                u32 off = (u32)(m0w + aRowOff) * 128 + aKb + (u32)kk * 32;
                off ^= (off >> 3) & 0x70;
                LDX4(qf, sb + A_Q + off);
            }
            u32 fk[4][4];
#pragma unroll
            for (int g = 0; g < 4; g++) {
                u32 off = (u32)(g * 16 + bRowOff) * 128 + bKb + (u32)kk * 32;
                off ^= (off >> 3) & 0x70;
                LDX4(fk[g], stg + 0 + off);
            }
#pragma unroll
            for (int ni = 0; ni < 8; ni++)
                MMA16816H(sacc[ni], qf,
                          fk[ni >> 1][(ni & 1) * 2], fk[ni >> 1][(ni & 1) * 2 + 1]);
        }

        // ---- causal mask (only last two tiles) ----
        if (c >= 2 * qb) {
#pragma unroll
            for (int ni = 0; ni < 8; ni++) {
                const int col = c * 64 + ni * 8 + (lane & 3) * 2;
                if (col > qi0)     sacc[ni][0] = NEGINF;
                if (col + 1 > qi0) sacc[ni][1] = NEGINF;
                if (col > qi0 + 8)     sacc[ni][2] = NEGINF;
                if (col + 1 > qi0 + 8) sacc[ni][3] = NEGINF;
            }
        }

        // ---- online softmax ----
        float mx0 = NEGINF, mx1 = NEGINF;
#pragma unroll
        for (int ni = 0; ni < 8; ni++) {
            mx0 = fmaxf(mx0, fmaxf(sacc[ni][0], sacc[ni][1]));
            mx1 = fmaxf(mx1, fmaxf(sacc[ni][2], sacc[ni][3]));
        }
        mx0 = fmaxf(mx0, __shfl_xor_sync(0xffffffffu, mx0, 1));
        mx0 = fmaxf(mx0, __shfl_xor_sync(0xffffffffu, mx0, 2));
        mx1 = fmaxf(mx1, __shfl_xor_sync(0xffffffffu, mx1, 1));
        mx1 = fmaxf(mx1, __shfl_xor_sync(0xffffffffu, mx1, 2));

        const float nm0 = fmaxf(m0, mx0), nm1 = fmaxf(m1, mx1);
        const float cr0 = __expf(m0 - nm0), cr1 = __expf(m1 - nm1);
        m0 = nm0; m1 = nm1;

        float s0 = 0.f, s1 = 0.f;
#pragma unroll
        for (int ni = 0; ni < 8; ni++) {
            sacc[ni][0] = __expf(sacc[ni][0] - nm0);
            sacc[ni][1] = __expf(sacc[ni][1] - nm0);
            sacc[ni][2] = __expf(sacc[ni][2] - nm1);
            sacc[ni][3] = __expf(sacc[ni][3] - nm1);
            s0 += sacc[ni][0] + sacc[ni][1];
            s1 += sacc[ni][2] + sacc[ni][3];
        }
        s0 += __shfl_xor_sync(0xffffffffu, s0, 1);
        s0 += __shfl_xor_sync(0xffffffffu, s0, 2);
        s1 += __shfl_xor_sync(0xffffffffu, s1, 1);
        s1 += __shfl_xor_sync(0xffffffffu, s1, 2);
        l0 = l0 * cr0 + s0;
        l1 = l1 * cr1 + s1;

#pragma unroll
        for (int ni = 0; ni < 8; ni++) {
            oacc[ni][0] *= cr0; oacc[ni][1] *= cr0;
            oacc[ni][2] *= cr1; oacc[ni][3] *= cr1;
        }

        // ---- O += P V (P single fp16, V hi+lo: 2 products) ----
#pragma unroll
        for (int kk = 0; kk < 4; kk++) {
            u32 ph[4];
            ph[0] = pack_h2(sacc[2 * kk][0],     sacc[2 * kk][1]);
            ph[1] = pack_h2(sacc[2 * kk][2],     sacc[2 * kk][3]);
            ph[2] = pack_h2(sacc[2 * kk + 1][0], sacc[2 * kk + 1][1]);
            ph[3] = pack_h2(sacc[2 * kk + 1][2], sacc[2 * kk + 1][3]);
#pragma unroll
            for (int nj = 0; nj < 4; nj++) {
                u32 fvh[4], fvl[4];
                u32 off = (u32)(kk * 16 + (lane & 15)) * 128 + (u32)nj * 32 + (u32)((lane >> 4) << 4);
                off ^= (off >> 3) & 0x70;
                LDX4T(fvh, stg + 8192 + off);
                LDX4T(fvl, stg + 16384 + off);
                MMA16816H(oacc[nj * 2 + 0], ph, fvh[0], fvh[1]);
                MMA16816H(oacc[nj * 2 + 1], ph, fvh[2], fvh[3]);
                MMA16816H(oacc[nj * 2 + 0], ph, fvl[0], fvl[1]);
                MMA16816H(oacc[nj * 2 + 1], ph, fvl[2], fvl[3]);
            }
        }
        __syncthreads();
    }

    // ---- epilogue: normalize, split fp16 hi/lo, write to g_ah/g_al ----
    const float inv0 = 1.f / l0, inv1 = 1.f / l1;
    const size_t r0off = ((size_t)b * Sc + qi0) * Dc + h * HDc;
    const size_t r1off = ((size_t)b * Sc + qi0 + 8) * Dc + h * HDc;
#pragma unroll
    for (int ni = 0; ni < 8; ni++) {
        const int col = ni * 8 + (lane & 3) * 2;
        u32 hv, lv;
        split_pack_h(oacc[ni][0] * inv0, oacc[ni][1] * inv0, hv, lv);
        *reinterpret_cast<u32*>(g_ah + r0off + col) = hv;
        *reinterpret_cast<u32*>(g_al + r0off + col) = lv;
        split_pack_h(oacc[ni][2] * inv1, oacc[ni][3] * inv1, hv, lv);
        *reinterpret_cast<u32*>(g_ah + r1off + col) = hv;
        *reinterpret_cast<u32*>(g_al + r1off + col) = lv;
    }
}

// ---------------------------------------------------------------------------
extern "C" void kernel_launch(void* const* d_in, const int* in_sizes, int n_in,
                              void* d_out, int out_size)
{
    const float* X     = (const float*)d_in[0];
    const float* W_qkv = (const float*)d_in[1];
    const float* b_qkv = (const float*)d_in[2];
    const float* W_out = (const float*)d_in[3];
    const float* b_out = (const float*)d_in[4];
    float* out = (float*)d_out;

    cudaFuncSetAttribute(gemm_mma<0>, cudaFuncAttributeMaxDynamicSharedMemorySize, GEMM_SMEM);
    cudaFuncSetAttribute(gemm_mma<1>, cudaFuncAttributeMaxDynamicSharedMemorySize, GEMM_SMEM);
    cudaFuncSetAttribute(attn_mma, cudaFuncAttributeMaxDynamicSharedMemorySize, ATT_SMEM);

    // fp16 splits
    split_rm<<<1024, 256>>>(X, Mtot * Dc / 4);
    split_tr<0><<<dim3(3 * Dc / 32, Dc / 32), dim3(32, 8)>>>(W_qkv, Dc, 3 * Dc);
    split_tr<1><<<dim3(Dc / 32, Dc / 32), dim3(32, 8)>>>(W_out, Dc, Dc);

    // 1) QKV projection -> fp16 Q(scaled)/K single, V hi/lo in [bh,s,hd]
    gemm_mma<0><<<dim3(3 * Dc / 64, Mtot / 128), 256, GEMM_SMEM>>>(b_qkv, nullptr, 3 * Dc, Dc);

    // 2) causal flash attention (fp16 tensor cores) -> g_ah/g_al (hi/lo, [b,s,D])
    attn_mma<<<dim3(Sc / 128, Bc * Hc), 256, ATT_SMEM>>>();

    // 3) out-proj -> d_out
    gemm_mma<1><<<dim3(Dc / 64, Mtot / 128), 256, GEMM_SMEM>>>(b_out, out, Dc, Dc);
}

// round 11
// speedup vs baseline: 1.7740x; 1.1750x over previous
#include <cuda_runtime.h>
#include <cuda_bf16.h>
#include <cuda_fp16.h>
#include <math.h>
#include <stdint.h>

// Problem constants
#define Bc   2
#define Sc   2048
#define Dc   1024
#define Hc   16
#define HDc  64
#define Mtot 4096
#define SCALE 0.03125f          // 1/sqrt(1024)
#define NEGINF (-1e30f)

typedef unsigned long long u64;
typedef uint32_t u32;

// ---------------- scratch (device globals; referenced ONLY in device code) --
__device__ __half g_q16[(size_t)Bc * Hc * Sc * HDc];   // fp16, pre-scaled
__device__ __half g_k16[(size_t)Bc * Hc * Sc * HDc];   // fp16
__device__ __half g_vh16[(size_t)Bc * Hc * Sc * HDc];  // fp16 hi
__device__ __half g_vl16[(size_t)Bc * Hc * Sc * HDc];  // fp16 lo

__device__ __half g_ah[(size_t)Mtot * Dc];             // A hi fp16 (X single / attn-out hi)
__device__ __half g_al[(size_t)Mtot * Dc];             // A lo fp16 (attn-out lo)
__device__ __half g_wq16[(size_t)3 * Dc * Dc];         // W_qkv^T fp16  [3072, 1024]
__device__ __half g_wo16[(size_t)Dc * Dc];             // W_out^T fp16  [1024, 1024]

// ---------------- PTX helpers (non-arch-specific, sm_80 class) --------------
__device__ __forceinline__ u32 smem_u32_of(const void* p) {
    u32 a;
    asm("{ .reg .u64 t; cvta.to.shared.u64 t, %1; cvt.u32.u64 %0, t; }" : "=r"(a) : "l"(p));
    return a;
}
__device__ __forceinline__ void cp16(u32 dst, const void* src) {
    asm volatile("cp.async.cg.shared.global [%0], [%1], 16;" :: "r"(dst), "l"(src));
}
#define CP_COMMIT() asm volatile("cp.async.commit_group;" ::: "memory")
#define CP_WAIT1()  asm volatile("cp.async.wait_group 1;" ::: "memory")
#define CP_WAIT0()  asm volatile("cp.async.wait_group 0;" ::: "memory")

#define LDX4(r, addr) \
    asm volatile("ldmatrix.sync.aligned.m8n8.x4.shared.b16 {%0,%1,%2,%3}, [%4];" \
        : "=r"((r)[0]), "=r"((r)[1]), "=r"((r)[2]), "=r"((r)[3]) : "r"(addr))
#define LDX4T(r, addr) \
    asm volatile("ldmatrix.sync.aligned.m8n8.x4.trans.shared.b16 {%0,%1,%2,%3}, [%4];" \
        : "=r"((r)[0]), "=r"((r)[1]), "=r"((r)[2]), "=r"((r)[3]) : "r"(addr))

#define MMA16816H(d, a, b0, b1) \
    asm volatile("mma.sync.aligned.m16n8k16.row.col.f32.f16.f16.f32 " \
        "{%0,%1,%2,%3}, {%4,%5,%6,%7}, {%8,%9}, {%0,%1,%2,%3};" \
        : "+f"((d)[0]), "+f"((d)[1]), "+f"((d)[2]), "+f"((d)[3]) \
        : "r"((a)[0]), "r"((a)[1]), "r"((a)[2]), "r"((a)[3]), "r"(b0), "r"(b1))

// split v0,v1 (fp32) -> packed fp16x2 hi + lo residual
__device__ __forceinline__ void split_pack_h(float v0, float v1, u32& h, u32& l) {
    __half2 hb = __floats2half2_rn(v0, v1);
    h = *reinterpret_cast<u32*>(&hb);
    float r0 = v0 - __low2float(hb);
    float r1 = v1 - __high2float(hb);
    __half2 lb = __floats2half2_rn(r0, r1);
    l = *reinterpret_cast<u32*>(&lb);
}
__device__ __forceinline__ u32 pack_h2(float v0, float v1) {
    __half2 hb = __floats2half2_rn(v0, v1);
    return *reinterpret_cast<u32*>(&hb);
}

// ---------------------------------------------------------------------------
// Split kernels
// ---------------------------------------------------------------------------
// fp32 X -> single fp16 into g_ah (lo not needed for QKV GEMM)
__global__ void split_x(const float* __restrict__ src, int n4)
{
    for (int i = blockIdx.x * blockDim.x + threadIdx.x; i < n4; i += gridDim.x * blockDim.x) {
        float4 v = reinterpret_cast<const float4*>(src)[i];
        uint2 hv;
        hv.x = pack_h2(v.x, v.y);
        hv.y = pack_h2(v.z, v.w);
        reinterpret_cast<uint2*>(g_ah)[i] = hv;
    }
}

// W [Kd, Nd] row-major -> single fp16 [Nd, Kd]. MODE 0 -> g_wq16, MODE 1 -> g_wo16.
template <int MODE>
__global__ void split_tr(const float* __restrict__ W, int Kd, int Nd)
{
    __half* dst = (MODE == 0) ? g_wq16 : g_wo16;
    __shared__ float t[32][33];
    const int n0 = blockIdx.x * 32, k0 = blockIdx.y * 32;
    const int tx = threadIdx.x, ty = threadIdx.y;
#pragma unroll
    for (int i = 0; i < 4; i++)
        t[ty + i * 8][tx] = W[(size_t)(k0 + ty + i * 8) * Nd + n0 + tx];
    __syncthreads();
#pragma unroll
    for (int i = 0; i < 4; i++) {
        const int nn = ty + i * 8;
        dst[(size_t)(n0 + nn) * Kd + k0 + tx] = __float2half_rn(t[tx][nn]);
    }
}

// ---------------------------------------------------------------------------
// mma.sync fp16 GEMM, 2 CTAs/SM. Tile 128x64, 8 warps, warp 32x32.
// MODE 0 (QKV): A single product (X fp16); epilogue -> fp16 Q(scaled)/K, V hi/lo.
// MODE 1 (out): A 2-product (attn hi/lo); fp32 + bias -> C.
// ---------------------------------------------------------------------------
#define KC        64
#define OFF_AH    0
#define OFF_AL    16384
#define OFF_B     32768
#define STAGE_B   40960          // 40 KB
#define GEMM_SMEM (2 * STAGE_B)  // 80 KB -> 2 CTAs/SM

template <int NPROD>
__device__ __forceinline__ void load_chunk(u32 stg,
    const __half* __restrict__ Ah, const __half* __restrict__ Al,
    const __half* __restrict__ Bw,
    int bm, int bn, int col0, int K, int tid)
{
    // A hi: 128 rows x 64 fp16 = 1024 vec16
#pragma unroll
    for (int i = 0; i < 4; i++) {
        const int idx = i * 256 + tid;
        const int r = (idx >> 3) & 127;
        const int cc = idx & 7;
        u32 off = (u32)((r << 7) + (cc << 4));
        off ^= (off >> 3) & 0x70;
        cp16(stg + OFF_AH + off, Ah + (size_t)(bm + r) * K + col0 + cc * 8);
    }
    if (NPROD == 2) {
#pragma unroll
        for (int i = 0; i < 4; i++) {
            const int idx = i * 256 + tid;
            const int r = (idx >> 3) & 127;
            const int cc = idx & 7;
            u32 off = (u32)((r << 7) + (cc << 4));
            off ^= (off >> 3) & 0x70;
            cp16(stg + OFF_AL + off, Al + (size_t)(bm + r) * K + col0 + cc * 8);
        }
    }
    // B: 64 rows x 64 fp16 = 512 vec16
#pragma unroll
    for (int i = 0; i < 2; i++) {
        const int idx = i * 256 + tid;
        const int r = (idx >> 3) & 63;
        const int cc = idx & 7;
        u32 off = (u32)((r << 7) + (cc << 4));
        off ^= (off >> 3) & 0x70;
        cp16(stg + OFF_B + off, Bw + (size_t)(bn + r) * K + col0 + cc * 8);
    }
}

template <int MODE>
__global__ __launch_bounds__(256, 2)
void gemm_mma(const float* __restrict__ bias, float* __restrict__ C, int N, int K)
{
    const int NPROD = (MODE == 0) ? 1 : 2;
    const __half* Ah = g_ah;
    const __half* Al = g_al;
    const __half* Bw = (MODE == 0) ? g_wq16 : g_wo16;

    extern __shared__ char smem[];
    const u32 sbase = smem_u32_of(smem);
    const int tid = threadIdx.x;
    const int bm = blockIdx.y * 128;
    const int bn = blockIdx.x * 64;
    const int lane = tid & 31, warp = tid >> 5;
    const int m0w = (warp >> 1) * 32;
    const int n0w = (warp & 1) * 32;

    float acc[2][4][4];
#pragma unroll
    for (int mi = 0; mi < 2; mi++)
#pragma unroll
        for (int ni = 0; ni < 4; ni++)
#pragma unroll
            for (int q = 0; q < 4; q++) acc[mi][ni][q] = 0.f;

    const int aRowOff = lane & 15;
    const u32 aKb = (u32)((lane >> 4) << 4);
    const int bRowOff = ((lane >> 4) & 1) * 8 + (lane & 7);
    const u32 bKb = (u32)(((lane >> 3) & 1) << 4);

    const int NC = K / KC;

    load_chunk<NPROD>(sbase, Ah, Al, Bw, bm, bn, 0, K, tid);
    CP_COMMIT();

    for (int c = 0; c < NC; c++) {
        const u32 stg = sbase + (u32)(c & 1) * STAGE_B;
        if (c + 1 < NC) {
            load_chunk<NPROD>(sbase + (u32)((c + 1) & 1) * STAGE_B, Ah, Al, Bw, bm, bn, (c + 1) * KC, K, tid);
            CP_COMMIT();
            CP_WAIT1();
        } else {
            CP_WAIT0();
        }
        __syncthreads();

#pragma unroll
        for (int k16 = 0; k16 < 4; k16++) {
            u32 fAh[2][4], fAl[2][4];
#pragma unroll
            for (int mi = 0; mi < 2; mi++) {
                u32 off = (u32)(m0w + mi * 16 + aRowOff) * 128 + aKb + (u32)k16 * 32;
                off ^= (off >> 3) & 0x70;
                LDX4(fAh[mi], stg + OFF_AH + off);
                if (NPROD == 2) LDX4(fAl[mi], stg + OFF_AL + off);
            }
            u32 fB[2][4];
#pragma unroll
            for (int bi = 0; bi < 2; bi++) {
                u32 off = (u32)(n0w + bi * 16 + bRowOff) * 128 + bKb + (u32)k16 * 32;
                off ^= (off >> 3) & 0x70;
                LDX4(fB[bi], stg + OFF_B + off);
            }
#pragma unroll
            for (int mi = 0; mi < 2; mi++)
#pragma unroll
                for (int ni = 0; ni < 4; ni++)
                    MMA16816H(acc[mi][ni], fAh[mi],
                              fB[ni >> 1][(ni & 1) * 2], fB[ni >> 1][(ni & 1) * 2 + 1]);
            if (NPROD == 2) {
#pragma unroll
                for (int mi = 0; mi < 2; mi++)
#pragma unroll
                    for (int ni = 0; ni < 4; ni++)
                        MMA16816H(acc[mi][ni], fAl[mi],
                                  fB[ni >> 1][(ni & 1) * 2], fB[ni >> 1][(ni & 1) * 2 + 1]);
            }
        }
        __syncthreads();
    }

#pragma unroll
    for (int ni = 0; ni < 4; ni++) {
        const int g = bn + n0w + ni * 8 + (lane & 3) * 2;
        const float bv0 = bias[g], bv1 = bias[g + 1];
        if (MODE == 1) {
#pragma unroll
            for (int mi = 0; mi < 2; mi++) {
                const int r0 = bm + m0w + mi * 16 + (lane >> 2);
                float2 v0 = {acc[mi][ni][0] + bv0, acc[mi][ni][1] + bv1};
                float2 v1 = {acc[mi][ni][2] + bv0, acc[mi][ni][3] + bv1};
                *reinterpret_cast<float2*>(C + (size_t)r0 * N + g) = v0;
                *reinterpret_cast<float2*>(C + (size_t)(r0 + 8) * N + g) = v1;
            }
        } else {
            const int qkv = g >> 10;
            const int h = (g & 1023) >> 6;
            const int c0 = g & 63;
#pragma unroll
            for (int mi = 0; mi < 2; mi++) {
#pragma unroll
                for (int half = 0; half < 2; half++) {
                    const int row = bm + m0w + mi * 16 + (lane >> 2) + half * 8;
                    const int b = row >> 11;
                    const int sI = row & (Sc - 1);
                    const float v0 = acc[mi][ni][half * 2 + 0] + bv0;
                    const float v1 = acc[mi][ni][half * 2 + 1] + bv1;
                    const size_t o = (((size_t)(b * Hc + h)) * Sc + sI) * HDc + c0;
                    if (qkv == 0) {
                        *reinterpret_cast<u32*>(g_q16 + o) = pack_h2(v0 * SCALE, v1 * SCALE);
                    } else if (qkv == 1) {
                        *reinterpret_cast<u32*>(g_k16 + o) = pack_h2(v0, v1);
                    } else {
                        u32 hv, lv;
                        split_pack_h(v0, v1, hv, lv);
                        *reinterpret_cast<u32*>(g_vh16 + o) = hv;
                        *reinterpret_cast<u32*>(g_vl16 + o) = lv;
                    }
                }
            }
        }
    }
}

// ---------------------------------------------------------------------------
// FlashAttention-2 with fp16 mma.sync: QK single-product, PV 2-product.
// CTA = 128 queries, 8 warps (16 rows each). Key tiles of 64.
// ---------------------------------------------------------------------------
#define A_Q    0                 // 16 KB: Q fp16, 128 x 64
#define A_STG  16384             // 2 stages x 24576: {K 8192, VH 8192, VL 8192}
#define STG_SZ 24576
#define ATT_SMEM (16384 + 2 * STG_SZ)   // 64 KB -> 2 CTAs/SM

__device__ __forceinline__ void attn_load_stage(u32 stg,
    const __half* Kk, const __half* Vh, const __half* Vl, int kt, int tid)
{
#pragma unroll
    for (int i = 0; i < 6; i++) {
        const int idx = i * 256 + tid;
        const int tile = idx >> 9;
        const int r = (idx >> 3) & 63;
        const int cc = idx & 7;
        u32 off = (u32)(r * 128 + cc * 16);
        off ^= (off >> 3) & 0x70;
        const __half* s = (tile == 0) ? Kk : ((tile == 1) ? Vh : Vl);
        cp16(stg + (u32)tile * 8192 + off, s + (size_t)(kt * 64 + r) * HDc + cc * 8);
    }
}

__global__ __launch_bounds__(256, 2)
void attn_mma()
{
    const int bh = blockIdx.y;
    const int qb = (int)gridDim.x - 1 - (int)blockIdx.x;   // big tiles first
    const int b = bh >> 4, h = bh & 15;

    extern __shared__ char smem[];
    const u32 sb = smem_u32_of(smem);
    const int tid = threadIdx.x, lane = tid & 31, warp = tid >> 5;
    const int m0w = warp * 16;

    const size_t bhoff = (size_t)bh * Sc * HDc;
    const __half* Qq = g_q16 + bhoff;
    const __half* Kk = g_k16 + bhoff;
    const __half* Vh = g_vh16 + bhoff;
    const __half* Vl = g_vl16 + bhoff;

    const int NT = 2 * qb + 2;

    // preload Q tile + stage 0
#pragma unroll
    for (int i = 0; i < 4; i++) {
        const int idx = i * 256 + tid;
        const int r = (idx >> 3) & 127;
        const int cc = idx & 7;
        u32 off = (u32)(r * 128 + cc * 16);
        off ^= (off >> 3) & 0x70;
        cp16(sb + A_Q + off, Qq + (size_t)(qb * 128 + r) * HDc + cc * 8);
    }
    attn_load_stage(sb + A_STG, Kk, Vh, Vl, 0, tid);
    CP_COMMIT();

    const int aRowOff = lane & 15;
    const u32 aKb = (u32)((lane >> 4) << 4);
    const int bRowOff = ((lane >> 4) & 1) * 8 + (lane & 7);
    const u32 bKb = (u32)(((lane >> 3) & 1) << 4);

    float oacc[8][4];
#pragma unroll
    for (int ni = 0; ni < 8; ni++)
#pragma unroll
        for (int q = 0; q < 4; q++) oacc[ni][q] = 0.f;
    float m0 = NEGINF, m1 = NEGINF, l0 = 0.f, l1 = 0.f;

    const int qi0 = qb * 128 + m0w + (lane >> 2);

    for (int c = 0; c < NT; c++) {
        const u32 stg = sb + A_STG + (u32)(c & 1) * STG_SZ;
        if (c + 1 < NT) {
            attn_load_stage(sb + A_STG + (u32)((c + 1) & 1) * STG_SZ, Kk, Vh, Vl, c + 1, tid);
            CP_COMMIT();
            CP_WAIT1();
        } else {
            CP_WAIT0();
        }
        __syncthreads();

        // ---- S = Q K^T (single product, fp16) ----
        float sacc[8][4];
#pragma unroll
        for (int ni = 0; ni < 8; ni++)
#pragma unroll
            for (int q = 0; q < 4; q++) sacc[ni][q] = 0.f;

#pragma unroll
        for (int kk = 0; kk < 4; kk++) {
            u32 qf[4];
            {
                u32 off = (u32)(m0w + aRowOff) * 128 + aKb + (u32)kk * 32;
                off ^= (off >> 3) & 0x70;
                LDX4(qf, sb + A_Q + off);
            }
            u32 fk[4][4];
#pragma unroll
            for (int g = 0; g < 4; g++) {
                u32 off = (u32)(g * 16 + bRowOff) * 128 + bKb + (u32)kk * 32;
                off ^= (off >> 3) & 0x70;
                LDX4(fk[g], stg + 0 + off);
            }
#pragma unroll
            for (int ni = 0; ni < 8; ni++)
                MMA16816H(sacc[ni], qf,
                          fk[ni >> 1][(ni & 1) * 2], fk[ni >> 1][(ni & 1) * 2 + 1]);
        }

        // ---- causal mask (only last two tiles) ----
        if (c >= 2 * qb) {
#pragma unroll
            for (int ni = 0; ni < 8; ni++) {
                const int col = c * 64 + ni * 8 + (lane & 3) * 2;
                if (col > qi0)     sacc[ni][0] = NEGINF;
                if (col + 1 > qi0) sacc[ni][1] = NEGINF;
                if (col > qi0 + 8)     sacc[ni][2] = NEGINF;
                if (col + 1 > qi0 + 8) sacc[ni][3] = NEGINF;
            }
        }

        // ---- online softmax ----
        float mx0 = NEGINF, mx1 = NEGINF;
#pragma unroll
        for (int ni = 0; ni < 8; ni++) {
            mx0 = fmaxf(mx0, fmaxf(sacc[ni][0], sacc[ni][1]));
            mx1 = fmaxf(mx1, fmaxf(sacc[ni][2], sacc[ni][3]));
        }
        mx0 = fmaxf(mx0, __shfl_xor_sync(0xffffffffu, mx0, 1));
        mx0 = fmaxf(mx0, __shfl_xor_sync(0xffffffffu, mx0, 2));
        mx1 = fmaxf(mx1, __shfl_xor_sync(0xffffffffu, mx1, 1));
        mx1 = fmaxf(mx1, __shfl_xor_sync(0xffffffffu, mx1, 2));

        const float nm0 = fmaxf(m0, mx0), nm1 = fmaxf(m1, mx1);
        const float cr0 = __expf(m0 - nm0), cr1 = __expf(m1 - nm1);
        m0 = nm0; m1 = nm1;

        float s0 = 0.f, s1 = 0.f;
#pragma unroll
        for (int ni = 0; ni < 8; ni++) {
            sacc[ni][0] = __expf(sacc[ni][0] - nm0);
            sacc[ni][1] = __expf(sacc[ni][1] - nm0);
            sacc[ni][2] = __expf(sacc[ni][2] - nm1);
            sacc[ni][3] = __expf(sacc[ni][3] - nm1);
            s0 += sacc[ni][0] + sacc[ni][1];
            s1 += sacc[ni][2] + sacc[ni][3];
        }
        s0 += __shfl_xor_sync(0xffffffffu, s0, 1);
        s0 += __shfl_xor_sync(0xffffffffu, s0, 2);
        s1 += __shfl_xor_sync(0xffffffffu, s1, 1);
        s1 += __shfl_xor_sync(0xffffffffu, s1, 2);
        l0 = l0 * cr0 + s0;
        l1 = l1 * cr1 + s1;

#pragma unroll
        for (int ni = 0; ni < 8; ni++) {
            oacc[ni][0] *= cr0; oacc[ni][1] *= cr0;
            oacc[ni][2] *= cr1; oacc[ni][3] *= cr1;
        }

        // ---- O += P V (P single fp16, V hi+lo: 2 products) ----
#pragma unroll
        for (int kk = 0; kk < 4; kk++) {
            u32 ph[4];
            ph[0] = pack_h2(sacc[2 * kk][0],     sacc[2 * kk][1]);
            ph[1] = pack_h2(sacc[2 * kk][2],     sacc[2 * kk][3]);
            ph[2] = pack_h2(sacc[2 * kk + 1][0], sacc[2 * kk + 1][1]);
            ph[3] = pack_h2(sacc[2 * kk + 1][2], sacc[2 * kk + 1][3]);
#pragma unroll
            for (int nj = 0; nj < 4; nj++) {
                u32 fvh[4], fvl[4];
                u32 off = (u32)(kk * 16 + (lane & 15)) * 128 + (u32)nj * 32 + (u32)((lane >> 4) << 4);
                off ^= (off >> 3) & 0x70;
                LDX4T(fvh, stg + 8192 + off);
                LDX4T(fvl, stg + 16384 + off);
                MMA16816H(oacc[nj * 2 + 0], ph, fvh[0], fvh[1]);
                MMA16816H(oacc[nj * 2 + 1], ph, fvh[2], fvh[3]);
                MMA16816H(oacc[nj * 2 + 0], ph, fvl[0], fvl[1]);
                MMA16816H(oacc[nj * 2 + 1], ph, fvl[2], fvl[3]);
            }
        }
        __syncthreads();
    }

    // ---- epilogue: normalize, split fp16 hi/lo, write to g_ah/g_al ----
    const float inv0 = 1.f / l0, inv1 = 1.f / l1;
    const size_t r0off = ((size_t)b * Sc + qi0) * Dc + h * HDc;
    const size_t r1off = ((size_t)b * Sc + qi0 + 8) * Dc + h * HDc;
#pragma unroll
    for (int ni = 0; ni < 8; ni++) {
        const int col = ni * 8 + (lane & 3) * 2;
        u32 hv, lv;
        split_pack_h(oacc[ni][0] * inv0, oacc[ni][1] * inv0, hv, lv);
        *reinterpret_cast<u32*>(g_ah + r0off + col) = hv;
        *reinterpret_cast<u32*>(g_al + r0off + col) = lv;
        split_pack_h(oacc[ni][2] * inv1, oacc[ni][3] * inv1, hv, lv);
        *reinterpret_cast<u32*>(g_ah + r1off + col) = hv;
        *reinterpret_cast<u32*>(g_al + r1off + col) = lv;
    }
}

// ---------------------------------------------------------------------------
extern "C" void kernel_launch(void* const* d_in, const int* in_sizes, int n_in,
                              void* d_out, int out_size)
{
    const float* X     = (const float*)d_in[0];
    const float* W_qkv = (const float*)d_in[1];
    const float* b_qkv = (const float*)d_in[2];
    const float* W_out = (const float*)d_in[3];
    const float* b_out = (const float*)d_in[4];
    float* out = (float*)d_out;

    cudaFuncSetAttribute(gemm_mma<0>, cudaFuncAttributeMaxDynamicSharedMemorySize, GEMM_SMEM);
    cudaFuncSetAttribute(gemm_mma<1>, cudaFuncAttributeMaxDynamicSharedMemorySize, GEMM_SMEM);
    cudaFuncSetAttribute(attn_mma, cudaFuncAttributeMaxDynamicSharedMemorySize, ATT_SMEM);

    // fp16 conversions
    split_x<<<1024, 256>>>(X, Mtot * Dc / 4);
    split_tr<0><<<dim3(3 * Dc / 32, Dc / 32), dim3(32, 8)>>>(W_qkv, Dc, 3 * Dc);
    split_tr<1><<<dim3(Dc / 32, Dc / 32), dim3(32, 8)>>>(W_out, Dc, Dc);

    // 1) QKV projection (single-product fp16) -> Q(scaled)/K single, V hi/lo
    gemm_mma<0><<<dim3(3 * Dc / 64, Mtot / 128), 256, GEMM_SMEM>>>(b_qkv, nullptr, 3 * Dc, Dc);

    // 2) causal flash attention (fp16 tensor cores) -> g_ah/g_al (hi/lo, [b,s,D])
    attn_mma<<<dim3(Sc / 128, Bc * Hc), 256, ATT_SMEM>>>();

    // 3) out-proj (2-product fp16) -> d_out
    gemm_mma<1><<<dim3(Dc / 64, Mtot / 128), 256, GEMM_SMEM>>>(b_out, out, Dc, Dc);
}

// round 12
// speedup vs baseline: 2.0439x; 1.1521x over previous
#include <cuda_runtime.h>
#include <cuda_bf16.h>
#include <cuda_fp16.h>
#include <math.h>
#include <stdint.h>

// Problem constants
#define Bc   2
#define Sc   2048
#define Dc   1024
#define Hc   16
#define HDc  64
#define Mtot 4096
#define SCALE 0.03125f          // 1/sqrt(1024)
#define NEGINF (-1e30f)

typedef unsigned long long u64;
typedef uint32_t u32;

// ---------------- scratch (device globals; referenced ONLY in device code) --
__device__ __half g_q16[(size_t)Bc * Hc * Sc * HDc];   // fp16, pre-scaled
__device__ __half g_k16[(size_t)Bc * Hc * Sc * HDc];   // fp16
__device__ __half g_v16[(size_t)Bc * Hc * Sc * HDc];   // fp16 (single)

__device__ __half g_ah[(size_t)Mtot * Dc];             // A hi fp16 (X single / attn-out hi)
__device__ __half g_al[(size_t)Mtot * Dc];             // A lo fp16 (attn-out lo)
__device__ __half g_wq16[(size_t)3 * Dc * Dc];         // W_qkv^T fp16  [3072, 1024]
__device__ __half g_wo16[(size_t)Dc * Dc];             // W_out^T fp16  [1024, 1024]

// ---------------- PTX helpers (non-arch-specific, sm_80 class) --------------
__device__ __forceinline__ u32 smem_u32_of(const void* p) {
    u32 a;
    asm("{ .reg .u64 t; cvta.to.shared.u64 t, %1; cvt.u32.u64 %0, t; }" : "=r"(a) : "l"(p));
    return a;
}
__device__ __forceinline__ void cp16(u32 dst, const void* src) {
    asm volatile("cp.async.cg.shared.global [%0], [%1], 16;" :: "r"(dst), "l"(src));
}
#define CP_COMMIT() asm volatile("cp.async.commit_group;" ::: "memory")
#define CP_WAIT1()  asm volatile("cp.async.wait_group 1;" ::: "memory")
#define CP_WAIT0()  asm volatile("cp.async.wait_group 0;" ::: "memory")

#define LDX4(r, addr) \
    asm volatile("ldmatrix.sync.aligned.m8n8.x4.shared.b16 {%0,%1,%2,%3}, [%4];" \
        : "=r"((r)[0]), "=r"((r)[1]), "=r"((r)[2]), "=r"((r)[3]) : "r"(addr))
#define LDX4T(r, addr) \
    asm volatile("ldmatrix.sync.aligned.m8n8.x4.trans.shared.b16 {%0,%1,%2,%3}, [%4];" \
        : "=r"((r)[0]), "=r"((r)[1]), "=r"((r)[2]), "=r"((r)[3]) : "r"(addr))

#define MMA16816H(d, a, b0, b1) \
    asm volatile("mma.sync.aligned.m16n8k16.row.col.f32.f16.f16.f32 " \
        "{%0,%1,%2,%3}, {%4,%5,%6,%7}, {%8,%9}, {%0,%1,%2,%3};" \
        : "+f"((d)[0]), "+f"((d)[1]), "+f"((d)[2]), "+f"((d)[3]) \
        : "r"((a)[0]), "r"((a)[1]), "r"((a)[2]), "r"((a)[3]), "r"(b0), "r"(b1))

// split v0,v1 (fp32) -> packed fp16x2 hi + lo residual
__device__ __forceinline__ void split_pack_h(float v0, float v1, u32& h, u32& l) {
    __half2 hb = __floats2half2_rn(v0, v1);
    h = *reinterpret_cast<u32*>(&hb);
    float r0 = v0 - __low2float(hb);
    float r1 = v1 - __high2float(hb);
    __half2 lb = __floats2half2_rn(r0, r1);
    l = *reinterpret_cast<u32*>(&lb);
}
__device__ __forceinline__ u32 pack_h2(float v0, float v1) {
    __half2 hb = __floats2half2_rn(v0, v1);
    return *reinterpret_cast<u32*>(&hb);
}

// ---------------------------------------------------------------------------
// Split kernels
// ---------------------------------------------------------------------------
__global__ void split_x(const float* __restrict__ src, int n4)
{
    for (int i = blockIdx.x * blockDim.x + threadIdx.x; i < n4; i += gridDim.x * blockDim.x) {
        float4 v = reinterpret_cast<const float4*>(src)[i];
        uint2 hv;
        hv.x = pack_h2(v.x, v.y);
        hv.y = pack_h2(v.z, v.w);
        reinterpret_cast<uint2*>(g_ah)[i] = hv;
    }
}

// W [Kd, Nd] row-major -> single fp16 [Nd, Kd]. MODE 0 -> g_wq16, MODE 1 -> g_wo16.
template <int MODE>
__global__ void split_tr(const float* __restrict__ W, int Kd, int Nd)
{
    __half* dst = (MODE == 0) ? g_wq16 : g_wo16;
    __shared__ float t[32][33];
    const int n0 = blockIdx.x * 32, k0 = blockIdx.y * 32;
    const int tx = threadIdx.x, ty = threadIdx.y;
#pragma unroll
    for (int i = 0; i < 4; i++)
        t[ty + i * 8][tx] = W[(size_t)(k0 + ty + i * 8) * Nd + n0 + tx];
    __syncthreads();
#pragma unroll
    for (int i = 0; i < 4; i++) {
        const int nn = ty + i * 8;
        dst[(size_t)(n0 + nn) * Kd + k0 + tx] = __float2half_rn(t[tx][nn]);
    }
}

// ---------------------------------------------------------------------------
// mma.sync fp16 GEMM, 2 CTAs/SM.
// MODE 0 (QKV): tile 128x128, warp 64x32, A single product; epi -> fp16 Q/K/V.
// MODE 1 (out): tile 128x64, warp 32x32, A 2-product (attn hi/lo); fp32 + bias.
// ---------------------------------------------------------------------------
#define KC 64

template <int MODE>
__device__ __forceinline__ void load_chunk(u32 stg,
    const __half* __restrict__ Ah, const __half* __restrict__ Al,
    const __half* __restrict__ Bw,
    int bm, int bn, int col0, int K, int tid)
{
    constexpr int NPROD = (MODE == 0) ? 1 : 2;
    constexpr u32 OFFB  = (MODE == 0) ? 16384u : 32768u;
    constexpr int BROWS = (MODE == 0) ? 128 : 64;
    // A hi: 128 rows x 64 fp16 = 1024 vec16
#pragma unroll
    for (int i = 0; i < 4; i++) {
        const int idx = i * 256 + tid;
        const int r = (idx >> 3) & 127;
        const int cc = idx & 7;
        u32 off = (u32)((r << 7) + (cc << 4));
        off ^= (off >> 3) & 0x70;
        cp16(stg + off, Ah + (size_t)(bm + r) * K + col0 + cc * 8);
    }
    if (NPROD == 2) {
#pragma unroll
        for (int i = 0; i < 4; i++) {
            const int idx = i * 256 + tid;
            const int r = (idx >> 3) & 127;
            const int cc = idx & 7;
            u32 off = (u32)((r << 7) + (cc << 4));
            off ^= (off >> 3) & 0x70;
            cp16(stg + 16384 + off, Al + (size_t)(bm + r) * K + col0 + cc * 8);
        }
    }
    // B: BROWS rows x 64 fp16
#pragma unroll
    for (int i = 0; i < BROWS / 32; i++) {
        const int idx = i * 256 + tid;
        const int r = (idx >> 3) & (BROWS - 1);
        const int cc = idx & 7;
        u32 off = (u32)((r << 7) + (cc << 4));
        off ^= (off >> 3) & 0x70;
        cp16(stg + OFFB + off, Bw + (size_t)(bn + r) * K + col0 + cc * 8);
    }
}

template <int MODE>
__global__ __launch_bounds__(256, 2)
void gemm_mma(const float* __restrict__ bias, float* __restrict__ C, int N, int K)
{
    constexpr int NPROD = (MODE == 0) ? 1 : 2;
    constexpr int MI    = (MODE == 0) ? 4 : 2;        // m-frags per warp
    constexpr int BNt   = (MODE == 0) ? 128 : 64;
    constexpr u32 STAGE = (MODE == 0) ? 32768u : 40960u;
    constexpr u32 OFFB  = (MODE == 0) ? 16384u : 32768u;

    const __half* Ah = g_ah;
    const __half* Al = g_al;
    const __half* Bw = (MODE == 0) ? g_wq16 : g_wo16;

    extern __shared__ char smem[];
    const u32 sbase = smem_u32_of(smem);
    const int tid = threadIdx.x;
    const int bm = blockIdx.y * 128;
    const int bn = blockIdx.x * BNt;
    const int lane = tid & 31, warp = tid >> 5;
    const int m0w = (MODE == 0) ? ((warp >> 2) * 64) : ((warp >> 1) * 32);
    const int n0w = (MODE == 0) ? ((warp & 3) * 32) : ((warp & 1) * 32);

    float acc[MI][4][4];
#pragma unroll
    for (int mi = 0; mi < MI; mi++)
#pragma unroll
        for (int ni = 0; ni < 4; ni++)
#pragma unroll
            for (int q = 0; q < 4; q++) acc[mi][ni][q] = 0.f;

    const int aRowOff = lane & 15;
    const u32 aKb = (u32)((lane >> 4) << 4);
    const int bRowOff = ((lane >> 4) & 1) * 8 + (lane & 7);
    const u32 bKb = (u32)(((lane >> 3) & 1) << 4);

    const int NC = K / KC;

    load_chunk<MODE>(sbase, Ah, Al, Bw, bm, bn, 0, K, tid);
    CP_COMMIT();

    for (int c = 0; c < NC; c++) {
        const u32 stg = sbase + (u32)(c & 1) * STAGE;
        if (c + 1 < NC) {
            load_chunk<MODE>(sbase + (u32)((c + 1) & 1) * STAGE, Ah, Al, Bw, bm, bn, (c + 1) * KC, K, tid);
            CP_COMMIT();
            CP_WAIT1();
        } else {
            CP_WAIT0();
        }
        __syncthreads();

#pragma unroll
        for (int k16 = 0; k16 < 4; k16++) {
            u32 fAh[MI][4], fAl[MI][4];
#pragma unroll
            for (int mi = 0; mi < MI; mi++) {
                u32 off = (u32)(m0w + mi * 16 + aRowOff) * 128 + aKb + (u32)k16 * 32;
                off ^= (off >> 3) & 0x70;
                LDX4(fAh[mi], stg + off);
                if (NPROD == 2) LDX4(fAl[mi], stg + 16384 + off);
            }
            u32 fB[2][4];
#pragma unroll
            for (int bi = 0; bi < 2; bi++) {
                u32 off = (u32)(n0w + bi * 16 + bRowOff) * 128 + bKb + (u32)k16 * 32;
                off ^= (off >> 3) & 0x70;
                LDX4(fB[bi], stg + OFFB + off);
            }
#pragma unroll
            for (int mi = 0; mi < MI; mi++)
#pragma unroll
                for (int ni = 0; ni < 4; ni++)
                    MMA16816H(acc[mi][ni], fAh[mi],
                              fB[ni >> 1][(ni & 1) * 2], fB[ni >> 1][(ni & 1) * 2 + 1]);
            if (NPROD == 2) {
#pragma unroll
                for (int mi = 0; mi < MI; mi++)
#pragma unroll
                    for (int ni = 0; ni < 4; ni++)
                        MMA16816H(acc[mi][ni], fAl[mi],
                                  fB[ni >> 1][(ni & 1) * 2], fB[ni >> 1][(ni & 1) * 2 + 1]);
            }
        }
        __syncthreads();
    }

#pragma unroll
    for (int ni = 0; ni < 4; ni++) {
        const int g = bn + n0w + ni * 8 + (lane & 3) * 2;
        const float bv0 = bias[g], bv1 = bias[g + 1];
        if (MODE == 1) {
#pragma unroll
            for (int mi = 0; mi < MI; mi++) {
                const int r0 = bm + m0w + mi * 16 + (lane >> 2);
                float2 v0 = {acc[mi][ni][0] + bv0, acc[mi][ni][1] + bv1};
                float2 v1 = {acc[mi][ni][2] + bv0, acc[mi][ni][3] + bv1};
                *reinterpret_cast<float2*>(C + (size_t)r0 * N + g) = v0;
                *reinterpret_cast<float2*>(C + (size_t)(r0 + 8) * N + g) = v1;
            }
        } else {
            const int qkv = g >> 10;
            const int h = (g & 1023) >> 6;
            const int c0 = g & 63;
#pragma unroll
            for (int mi = 0; mi < MI; mi++) {
#pragma unroll
                for (int half = 0; half < 2; half++) {
                    const int row = bm + m0w + mi * 16 + (lane >> 2) + half * 8;
                    const int b = row >> 11;
                    const int sI = row & (Sc - 1);
                    const float v0 = acc[mi][ni][half * 2 + 0] + bv0;
                    const float v1 = acc[mi][ni][half * 2 + 1] + bv1;
                    const size_t o = (((size_t)(b * Hc + h)) * Sc + sI) * HDc + c0;
                    if (qkv == 0) {
                        *reinterpret_cast<u32*>(g_q16 + o) = pack_h2(v0 * SCALE, v1 * SCALE);
                    } else if (qkv == 1) {
                        *reinterpret_cast<u32*>(g_k16 + o) = pack_h2(v0, v1);
                    } else {
                        *reinterpret_cast<u32*>(g_v16 + o) = pack_h2(v0, v1);
                    }
                }
            }
        }
    }
}

// ---------------------------------------------------------------------------
// FlashAttention-2, fp16 mma.sync: QK single, PV single (V fp16).
// CTA = 128 queries, 8 warps (16 rows each). Key tiles of 64.
// ---------------------------------------------------------------------------
#define A_Q    0                 // 16 KB: Q fp16, 128 x 64
#define A_STG  16384             // 2 stages x 16384: {K 8192, V 8192}
#define STG_SZ 16384
#define ATT_SMEM (16384 + 2 * STG_SZ)   // 48 KB -> 2+ CTAs/SM

__device__ __forceinline__ void attn_load_stage(u32 stg,
    const __half* Kk, const __half* Vv, int kt, int tid)
{
    // 1024 vec16: tile 0 = K, 1 = V (each 64 rows x 64 fp16 = 8 KB)
#pragma unroll
    for (int i = 0; i < 4; i++) {
        const int idx = i * 256 + tid;
        const int tile = idx >> 9;          // 0,0,1,1 per i
        const int r = (idx >> 3) & 63;
        const int cc = idx & 7;
        u32 off = (u32)(r * 128 + cc * 16);
        off ^= (off >> 3) & 0x70;
        const __half* s = (tile == 0) ? Kk : Vv;
        cp16(stg + (u32)tile * 8192 + off, s + (size_t)(kt * 64 + r) * HDc + cc * 8);
    }
}

__global__ __launch_bounds__(256, 2)
void attn_mma()
{
    const int bh = blockIdx.y;
    const int qb = (int)gridDim.x - 1 - (int)blockIdx.x;   // big tiles first
    const int b = bh >> 4, h = bh & 15;

    extern __shared__ char smem[];
    const u32 sb = smem_u32_of(smem);
    const int tid = threadIdx.x, lane = tid & 31, warp = tid >> 5;
    const int m0w = warp * 16;

    const size_t bhoff = (size_t)bh * Sc * HDc;
    const __half* Qq = g_q16 + bhoff;
    const __half* Kk = g_k16 + bhoff;
    const __half* Vv = g_v16 + bhoff;

    const int NT = 2 * qb + 2;

    // preload Q tile + stage 0
#pragma unroll
    for (int i = 0; i < 4; i++) {
        const int idx = i * 256 + tid;
        const int r = (idx >> 3) & 127;
        const int cc = idx & 7;
        u32 off = (u32)(r * 128 + cc * 16);
        off ^= (off >> 3) & 0x70;
        cp16(sb + A_Q + off, Qq + (size_t)(qb * 128 + r) * HDc + cc * 8);
    }
    attn_load_stage(sb + A_STG, Kk, Vv, 0, tid);
    CP_COMMIT();

    const int aRowOff = lane & 15;
    const u32 aKb = (u32)((lane >> 4) << 4);
    const int bRowOff = ((lane >> 4) & 1) * 8 + (lane & 7);
    const u32 bKb = (u32)(((lane >> 3) & 1) << 4);

    float oacc[8][4];
#pragma unroll
    for (int ni = 0; ni < 8; ni++)
#pragma unroll
        for (int q = 0; q < 4; q++) oacc[ni][q] = 0.f;
    float m0 = NEGINF, m1 = NEGINF, l0 = 0.f, l1 = 0.f;

    const int qi0 = qb * 128 + m0w + (lane >> 2);

    for (int c = 0; c < NT; c++) {
        const u32 stg = sb + A_STG + (u32)(c & 1) * STG_SZ;
        if (c + 1 < NT) {
            attn_load_stage(sb + A_STG + (u32)((c + 1) & 1) * STG_SZ, Kk, Vv, c + 1, tid);
            CP_COMMIT();
            CP_WAIT1();
        } else {
            CP_WAIT0();
        }
        __syncthreads();

        // ---- S = Q K^T (single product, fp16) ----
        float sacc[8][4];
#pragma unroll
        for (int ni = 0; ni < 8; ni++)
#pragma unroll
            for (int q = 0; q < 4; q++) sacc[ni][q] = 0.f;

#pragma unroll
        for (int kk = 0; kk < 4; kk++) {
            u32 qf[4];
            {
                u32 off = (u32)(m0w + aRowOff) * 128 + aKb + (u32)kk * 32;
                off ^= (off >> 3) & 0x70;
                LDX4(qf, sb + A_Q + off);
            }
            u32 fk[4][4];
#pragma unroll
            for (int g = 0; g < 4; g++) {
                u32 off = (u32)(g * 16 + bRowOff) * 128 + bKb + (u32)kk * 32;
                off ^= (off >> 3) & 0x70;
                LDX4(fk[g], stg + 0 + off);
            }
#pragma unroll
            for (int ni = 0; ni < 8; ni++)
                MMA16816H(sacc[ni], qf,
                          fk[ni >> 1][(ni & 1) * 2], fk[ni >> 1][(ni & 1) * 2 + 1]);
        }

        // ---- causal mask (only last two tiles) ----
        if (c >= 2 * qb) {
#pragma unroll
            for (int ni = 0; ni < 8; ni++) {
                const int col = c * 64 + ni * 8 + (lane & 3) * 2;
                if (col > qi0)     sacc[ni][0] = NEGINF;
                if (col + 1 > qi0) sacc[ni][1] = NEGINF;
                if (col > qi0 + 8)     sacc[ni][2] = NEGINF;
                if (col + 1 > qi0 + 8) sacc[ni][3] = NEGINF;
            }
        }

        // ---- online softmax ----
        float mx0 = NEGINF, mx1 = NEGINF;
#pragma unroll
        for (int ni = 0; ni < 8; ni++) {
            mx0 = fmaxf(mx0, fmaxf(sacc[ni][0], sacc[ni][1]));
            mx1 = fmaxf(mx1, fmaxf(sacc[ni][2], sacc[ni][3]));
        }
        mx0 = fmaxf(mx0, __shfl_xor_sync(0xffffffffu, mx0, 1));
        mx0 = fmaxf(mx0, __shfl_xor_sync(0xffffffffu, mx0, 2));
        mx1 = fmaxf(mx1, __shfl_xor_sync(0xffffffffu, mx1, 1));
        mx1 = fmaxf(mx1, __shfl_xor_sync(0xffffffffu, mx1, 2));

        const float nm0 = fmaxf(m0, mx0), nm1 = fmaxf(m1, mx1);
        const float cr0 = __expf(m0 - nm0), cr1 = __expf(m1 - nm1);
        m0 = nm0; m1 = nm1;

        float s0 = 0.f, s1 = 0.f;
#pragma unroll
        for (int ni = 0; ni < 8; ni++) {
            sacc[ni][0] = __expf(sacc[ni][0] - nm0);
            sacc[ni][1] = __expf(sacc[ni][1] - nm0);
            sacc[ni][2] = __expf(sacc[ni][2] - nm1);
            sacc[ni][3] = __expf(sacc[ni][3] - nm1);
            s0 += sacc[ni][0] + sacc[ni][1];
            s1 += sacc[ni][2] + sacc[ni][3];
        }
        s0 += __shfl_xor_sync(0xffffffffu, s0, 1);
        s0 += __shfl_xor_sync(0xffffffffu, s0, 2);
        s1 += __shfl_xor_sync(0xffffffffu, s1, 1);
        s1 += __shfl_xor_sync(0xffffffffu, s1, 2);
        l0 = l0 * cr0 + s0;
        l1 = l1 * cr1 + s1;

#pragma unroll
        for (int ni = 0; ni < 8; ni++) {
            oacc[ni][0] *= cr0; oacc[ni][1] *= cr0;
            oacc[ni][2] *= cr1; oacc[ni][3] *= cr1;
        }

        // ---- O += P V (P single fp16, V single) ----
#pragma unroll
        for (int kk = 0; kk < 4; kk++) {
            u32 ph[4];
            ph[0] = pack_h2(sacc[2 * kk][0],     sacc[2 * kk][1]);
            ph[1] = pack_h2(sacc[2 * kk][2],     sacc[2 * kk][3]);
            ph[2] = pack_h2(sacc[2 * kk + 1][0], sacc[2 * kk + 1][1]);
            ph[3] = pack_h2(sacc[2 * kk + 1][2], sacc[2 * kk + 1][3]);
#pragma unroll
            for (int nj = 0; nj < 4; nj++) {
                u32 fv[4];
                u32 off = (u32)(kk * 16 + (lane & 15)) * 128 + (u32)nj * 32 + (u32)((lane >> 4) << 4);
                off ^= (off >> 3) & 0x70;
                LDX4T(fv, stg + 8192 + off);
                MMA16816H(oacc[nj * 2 + 0], ph, fv[0], fv[1]);
                MMA16816H(oacc[nj * 2 + 1], ph, fv[2], fv[3]);
            }
        }
        __syncthreads();
    }

    // ---- epilogue: normalize, split fp16 hi/lo, write to g_ah/g_al ----
    const float inv0 = 1.f / l0, inv1 = 1.f / l1;
    const size_t r0off = ((size_t)b * Sc + qi0) * Dc + h * HDc;
    const size_t r1off = ((size_t)b * Sc + qi0 + 8) * Dc + h * HDc;
#pragma unroll
    for (int ni = 0; ni < 8; ni++) {
        const int col = ni * 8 + (lane & 3) * 2;
        u32 hv, lv;
        split_pack_h(oacc[ni][0] * inv0, oacc[ni][1] * inv0, hv, lv);
        *reinterpret_cast<u32*>(g_ah + r0off + col) = hv;
        *reinterpret_cast<u32*>(g_al + r0off + col) = lv;
        split_pack_h(oacc[ni][2] * inv1, oacc[ni][3] * inv1, hv, lv);
        *reinterpret_cast<u32*>(g_ah + r1off + col) = hv;
        *reinterpret_cast<u32*>(g_al + r1off + col) = lv;
    }
}

// ---------------------------------------------------------------------------
extern "C" void kernel_launch(void* const* d_in, const int* in_sizes, int n_in,
                              void* d_out, int out_size)
{
    const float* X     = (const float*)d_in[0];
    const float* W_qkv = (const float*)d_in[1];
    const float* b_qkv = (const float*)d_in[2];
    const float* W_out = (const float*)d_in[3];
    const float* b_out = (const float*)d_in[4];
    float* out = (float*)d_out;

    cudaFuncSetAttribute(gemm_mma<0>, cudaFuncAttributeMaxDynamicSharedMemorySize, 2 * 32768);
    cudaFuncSetAttribute(gemm_mma<1>, cudaFuncAttributeMaxDynamicSharedMemorySize, 2 * 40960);
    cudaFuncSetAttribute(attn_mma, cudaFuncAttributeMaxDynamicSharedMemorySize, ATT_SMEM);

    // fp16 conversions
    split_x<<<1024, 256>>>(X, Mtot * Dc / 4);
    split_tr<0><<<dim3(3 * Dc / 32, Dc / 32), dim3(32, 8)>>>(W_qkv, Dc, 3 * Dc);
    split_tr<1><<<dim3(Dc / 32, Dc / 32), dim3(32, 8)>>>(W_out, Dc, Dc);

    // 1) QKV projection (single-product fp16, 128x128 tile) -> Q(scaled)/K/V fp16
    gemm_mma<0><<<dim3(3 * Dc / 128, Mtot / 128), 256, 2 * 32768>>>(b_qkv, nullptr, 3 * Dc, Dc);

    // 2) causal flash attention (fp16 tensor cores) -> g_ah/g_al (hi/lo, [b,s,D])
    attn_mma<<<dim3(Sc / 128, Bc * Hc), 256, ATT_SMEM>>>();

    // 3) out-proj (2-product fp16, 128x64 tile) -> d_out
    gemm_mma<1><<<dim3(Dc / 64, Mtot / 128), 256, 2 * 40960>>>(b_out, out, Dc, Dc);
}

// round 13
// speedup vs baseline: 2.2948x; 1.1228x over previous
#include <cuda_runtime.h>
#include <cuda_bf16.h>
#include <cuda_fp16.h>
#include <math.h>
#include <stdint.h>

// Problem constants
#define Bc   2
#define Sc   2048
#define Dc   1024
#define Hc   16
#define HDc  64
#define Mtot 4096
#define SCALE 0.03125f          // 1/sqrt(1024)
#define NEGINF (-1e30f)

typedef unsigned long long u64;
typedef uint32_t u32;

// ---------------- scratch (device globals; referenced ONLY in device code) --
__device__ __half g_q16[(size_t)Bc * Hc * Sc * HDc];   // fp16, pre-scaled
__device__ __half g_k16[(size_t)Bc * Hc * Sc * HDc];   // fp16
__device__ __half g_v16[(size_t)Bc * Hc * Sc * HDc];   // fp16

__device__ __half g_a16[(size_t)Mtot * Dc];            // A fp16 (X, then attn out)
__device__ __half g_wq16[(size_t)3 * Dc * Dc];         // W_qkv^T fp16  [3072, 1024]
__device__ __half g_wo16[(size_t)Dc * Dc];             // W_out^T fp16  [1024, 1024]

// ---------------- PTX helpers (non-arch-specific, sm_80 class) --------------
__device__ __forceinline__ u32 smem_u32_of(const void* p) {
    u32 a;
    asm("{ .reg .u64 t; cvta.to.shared.u64 t, %1; cvt.u32.u64 %0, t; }" : "=r"(a) : "l"(p));
    return a;
}
__device__ __forceinline__ void cp16(u32 dst, const void* src) {
    asm volatile("cp.async.cg.shared.global [%0], [%1], 16;" :: "r"(dst), "l"(src));
}
#define CP_COMMIT() asm volatile("cp.async.commit_group;" ::: "memory")
#define CP_WAIT1()  asm volatile("cp.async.wait_group 1;" ::: "memory")
#define CP_WAIT0()  asm volatile("cp.async.wait_group 0;" ::: "memory")

#define LDX4(r, addr) \
    asm volatile("ldmatrix.sync.aligned.m8n8.x4.shared.b16 {%0,%1,%2,%3}, [%4];" \
        : "=r"((r)[0]), "=r"((r)[1]), "=r"((r)[2]), "=r"((r)[3]) : "r"(addr))
#define LDX4T(r, addr) \
    asm volatile("ldmatrix.sync.aligned.m8n8.x4.trans.shared.b16 {%0,%1,%2,%3}, [%4];" \
        : "=r"((r)[0]), "=r"((r)[1]), "=r"((r)[2]), "=r"((r)[3]) : "r"(addr))

#define MMA16816H(d, a, b0, b1) \
    asm volatile("mma.sync.aligned.m16n8k16.row.col.f32.f16.f16.f32 " \
        "{%0,%1,%2,%3}, {%4,%5,%6,%7}, {%8,%9}, {%0,%1,%2,%3};" \
        : "+f"((d)[0]), "+f"((d)[1]), "+f"((d)[2]), "+f"((d)[3]) \
        : "r"((a)[0]), "r"((a)[1]), "r"((a)[2]), "r"((a)[3]), "r"(b0), "r"(b1))

__device__ __forceinline__ u32 pack_h2(float v0, float v1) {
    __half2 hb = __floats2half2_rn(v0, v1);
    return *reinterpret_cast<u32*>(&hb);
}

// ---------------------------------------------------------------------------
// Conversion kernels
// ---------------------------------------------------------------------------
__global__ void split_x(const float* __restrict__ src, int n4)
{
    for (int i = blockIdx.x * blockDim.x + threadIdx.x; i < n4; i += gridDim.x * blockDim.x) {
        float4 v = reinterpret_cast<const float4*>(src)[i];
        uint2 hv;
        hv.x = pack_h2(v.x, v.y);
        hv.y = pack_h2(v.z, v.w);
        reinterpret_cast<uint2*>(g_a16)[i] = hv;
    }
}

// W [Kd, Nd] row-major -> single fp16 [Nd, Kd]. MODE 0 -> g_wq16, MODE 1 -> g_wo16.
template <int MODE>
__global__ void split_tr(const float* __restrict__ W, int Kd, int Nd)
{
    __half* dst = (MODE == 0) ? g_wq16 : g_wo16;
    __shared__ float t[32][33];
    const int n0 = blockIdx.x * 32, k0 = blockIdx.y * 32;
    const int tx = threadIdx.x, ty = threadIdx.y;
#pragma unroll
    for (int i = 0; i < 4; i++)
        t[ty + i * 8][tx] = W[(size_t)(k0 + ty + i * 8) * Nd + n0 + tx];
    __syncthreads();
#pragma unroll
    for (int i = 0; i < 4; i++) {
        const int nn = ty + i * 8;
        dst[(size_t)(n0 + nn) * Kd + k0 + tx] = __float2half_rn(t[tx][nn]);
    }
}

// ---------------------------------------------------------------------------
// mma.sync fp16 single-product GEMM, 2 CTAs/SM. Tile 128x128, warp 64x32.
// MODE 0 (QKV): epilogue -> fp16 Q(scaled)/K/V.  MODE 1 (out): fp32 + bias -> C.
// ---------------------------------------------------------------------------
#define KC      64
#define OFFB    16384u
#define STAGE   32768u
#define GEMM_SMEM (2 * 32768)

__device__ __forceinline__ void load_chunk(u32 stg,
    const __half* __restrict__ Aa, const __half* __restrict__ Bw,
    int bm, int bn, int col0, int K, int tid)
{
    // A: 128 rows x 64 fp16 = 1024 vec16
#pragma unroll
    for (int i = 0; i < 4; i++) {
        const int idx = i * 256 + tid;
        const int r = (idx >> 3) & 127;
        const int cc = idx & 7;
        u32 off = (u32)((r << 7) + (cc << 4));
        off ^= (off >> 3) & 0x70;
        cp16(stg + off, Aa + (size_t)(bm + r) * K + col0 + cc * 8);
    }
    // B: 128 rows x 64 fp16 = 1024 vec16
#pragma unroll
    for (int i = 0; i < 4; i++) {
        const int idx = i * 256 + tid;
        const int r = (idx >> 3) & 127;
        const int cc = idx & 7;
        u32 off = (u32)((r << 7) + (cc << 4));
        off ^= (off >> 3) & 0x70;
        cp16(stg + OFFB + off, Bw + (size_t)(bn + r) * K + col0 + cc * 8);
    }
}

template <int MODE>
__global__ __launch_bounds__(256, 2)
void gemm_mma(const float* __restrict__ bias, float* __restrict__ C, int N, int K)
{
    const __half* Aa = g_a16;
    const __half* Bw = (MODE == 0) ? g_wq16 : g_wo16;

    extern __shared__ char smem[];
    const u32 sbase = smem_u32_of(smem);
    const int tid = threadIdx.x;
    const int bm = blockIdx.y * 128;
    const int bn = blockIdx.x * 128;
    const int lane = tid & 31, warp = tid >> 5;
    const int m0w = (warp >> 2) * 64;
    const int n0w = (warp & 3) * 32;

    float acc[4][4][4];
#pragma unroll
    for (int mi = 0; mi < 4; mi++)
#pragma unroll
        for (int ni = 0; ni < 4; ni++)
#pragma unroll
            for (int q = 0; q < 4; q++) acc[mi][ni][q] = 0.f;

    const int aRowOff = lane & 15;
    const u32 aKb = (u32)((lane >> 4) << 4);
    const int bRowOff = ((lane >> 4) & 1) * 8 + (lane & 7);
    const u32 bKb = (u32)(((lane >> 3) & 1) << 4);

    const int NC = K / KC;

    load_chunk(sbase, Aa, Bw, bm, bn, 0, K, tid);
    CP_COMMIT();

    for (int c = 0; c < NC; c++) {
        const u32 stg = sbase + (u32)(c & 1) * STAGE;
        if (c + 1 < NC) {
            load_chunk(sbase + (u32)((c + 1) & 1) * STAGE, Aa, Bw, bm, bn, (c + 1) * KC, K, tid);
            CP_COMMIT();
            CP_WAIT1();
        } else {
            CP_WAIT0();
        }
        __syncthreads();

#pragma unroll
        for (int k16 = 0; k16 < 4; k16++) {
            u32 fA[4][4];
#pragma unroll
            for (int mi = 0; mi < 4; mi++) {
                u32 off = (u32)(m0w + mi * 16 + aRowOff) * 128 + aKb + (u32)k16 * 32;
                off ^= (off >> 3) & 0x70;
                LDX4(fA[mi], stg + off);
            }
            u32 fB[2][4];
#pragma unroll
            for (int bi = 0; bi < 2; bi++) {
                u32 off = (u32)(n0w + bi * 16 + bRowOff) * 128 + bKb + (u32)k16 * 32;
                off ^= (off >> 3) & 0x70;
                LDX4(fB[bi], stg + OFFB + off);
            }
#pragma unroll
            for (int mi = 0; mi < 4; mi++)
#pragma unroll
                for (int ni = 0; ni < 4; ni++)
                    MMA16816H(acc[mi][ni], fA[mi],
                              fB[ni >> 1][(ni & 1) * 2], fB[ni >> 1][(ni & 1) * 2 + 1]);
        }
        __syncthreads();
    }

#pragma unroll
    for (int ni = 0; ni < 4; ni++) {
        const int g = bn + n0w + ni * 8 + (lane & 3) * 2;
        const float bv0 = bias[g], bv1 = bias[g + 1];
        if (MODE == 1) {
#pragma unroll
            for (int mi = 0; mi < 4; mi++) {
                const int r0 = bm + m0w + mi * 16 + (lane >> 2);
                float2 v0 = {acc[mi][ni][0] + bv0, acc[mi][ni][1] + bv1};
                float2 v1 = {acc[mi][ni][2] + bv0, acc[mi][ni][3] + bv1};
                *reinterpret_cast<float2*>(C + (size_t)r0 * N + g) = v0;
                *reinterpret_cast<float2*>(C + (size_t)(r0 + 8) * N + g) = v1;
            }
        } else {
            const int qkv = g >> 10;
            const int h = (g & 1023) >> 6;
            const int c0 = g & 63;
            __half* dstB = (qkv == 0) ? g_q16 : ((qkv == 1) ? g_k16 : g_v16);
            const float scl = (qkv == 0) ? SCALE : 1.f;
#pragma unroll
            for (int mi = 0; mi < 4; mi++) {
#pragma unroll
                for (int half = 0; half < 2; half++) {
                    const int row = bm + m0w + mi * 16 + (lane >> 2) + half * 8;
                    const int b = row >> 11;
                    const int sI = row & (Sc - 1);
                    const float v0 = (acc[mi][ni][half * 2 + 0] + bv0) * scl;
                    const float v1 = (acc[mi][ni][half * 2 + 1] + bv1) * scl;
                    const size_t o = (((size_t)(b * Hc + h)) * Sc + sI) * HDc + c0;
                    *reinterpret_cast<u32*>(dstB + o) = pack_h2(v0, v1);
                }
            }
        }
    }
}

// ---------------------------------------------------------------------------
// FlashAttention-2, fp16 mma.sync: QK single, PV single.
// CTA = 128 queries, 8 warps (16 rows each). Key tiles of 64.
// ---------------------------------------------------------------------------
#define A_Q    0                 // 16 KB: Q fp16, 128 x 64
#define A_STG  16384             // 2 stages x 16384: {K 8192, V 8192}
#define STG_SZ 16384
#define ATT_SMEM (16384 + 2 * STG_SZ)   // 48 KB

__device__ __forceinline__ void attn_load_stage(u32 stg,
    const __half* Kk, const __half* Vv, int kt, int tid)
{
#pragma unroll
    for (int i = 0; i < 4; i++) {
        const int idx = i * 256 + tid;
        const int tile = idx >> 9;
        const int r = (idx >> 3) & 63;
        const int cc = idx & 7;
        u32 off = (u32)(r * 128 + cc * 16);
        off ^= (off >> 3) & 0x70;
        const __half* s = (tile == 0) ? Kk : Vv;
        cp16(stg + (u32)tile * 8192 + off, s + (size_t)(kt * 64 + r) * HDc + cc * 8);
    }
}

__global__ __launch_bounds__(256, 2)
void attn_mma()
{
    const int bh = blockIdx.y;
    const int qb = (int)gridDim.x - 1 - (int)blockIdx.x;   // big tiles first
    const int b = bh >> 4, h = bh & 15;

    extern __shared__ char smem[];
    const u32 sb = smem_u32_of(smem);
    const int tid = threadIdx.x, lane = tid & 31, warp = tid >> 5;
    const int m0w = warp * 16;

    const size_t bhoff = (size_t)bh * Sc * HDc;
    const __half* Qq = g_q16 + bhoff;
    const __half* Kk = g_k16 + bhoff;
    const __half* Vv = g_v16 + bhoff;

    const int NT = 2 * qb + 2;

    // preload Q tile + stage 0
#pragma unroll
    for (int i = 0; i < 4; i++) {
        const int idx = i * 256 + tid;
        const int r = (idx >> 3) & 127;
        const int cc = idx & 7;
        u32 off = (u32)(r * 128 + cc * 16);
        off ^= (off >> 3) & 0x70;
        cp16(sb + A_Q + off, Qq + (size_t)(qb * 128 + r) * HDc + cc * 8);
    }
    attn_load_stage(sb + A_STG, Kk, Vv, 0, tid);
    CP_COMMIT();

    const int aRowOff = lane & 15;
    const u32 aKb = (u32)((lane >> 4) << 4);
    const int bRowOff = ((lane >> 4) & 1) * 8 + (lane & 7);
    const u32 bKb = (u32)(((lane >> 3) & 1) << 4);

    float oacc[8][4];
#pragma unroll
    for (int ni = 0; ni < 8; ni++)
#pragma unroll
        for (int q = 0; q < 4; q++) oacc[ni][q] = 0.f;
    float m0 = NEGINF, m1 = NEGINF, l0 = 0.f, l1 = 0.f;

    const int qi0 = qb * 128 + m0w + (lane >> 2);

    for (int c = 0; c < NT; c++) {
        const u32 stg = sb + A_STG + (u32)(c & 1) * STG_SZ;
        if (c + 1 < NT) {
            attn_load_stage(sb + A_STG + (u32)((c + 1) & 1) * STG_SZ, Kk, Vv, c + 1, tid);
            CP_COMMIT();
            CP_WAIT1();
        } else {
            CP_WAIT0();
        }
        __syncthreads();

        // ---- S = Q K^T ----
        float sacc[8][4];
#pragma unroll
        for (int ni = 0; ni < 8; ni++)
#pragma unroll
            for (int q = 0; q < 4; q++) sacc[ni][q] = 0.f;

#pragma unroll
        for (int kk = 0; kk < 4; kk++) {
            u32 qf[4];
            {
                u32 off = (u32)(m0w + aRowOff) * 128 + aKb + (u32)kk * 32;
                off ^= (off >> 3) & 0x70;
                LDX4(qf, sb + A_Q + off);
            }
            u32 fk[4][4];
#pragma unroll
            for (int g = 0; g < 4; g++) {
                u32 off = (u32)(g * 16 + bRowOff) * 128 + bKb + (u32)kk * 32;
                off ^= (off >> 3) & 0x70;
                LDX4(fk[g], stg + 0 + off);
            }
#pragma unroll
            for (int ni = 0; ni < 8; ni++)
                MMA16816H(sacc[ni], qf,
                          fk[ni >> 1][(ni & 1) * 2], fk[ni >> 1][(ni & 1) * 2 + 1]);
        }

        // ---- causal mask (only last two tiles) ----
        if (c >= 2 * qb) {
#pragma unroll
            for (int ni = 0; ni < 8; ni++) {
                const int col = c * 64 + ni * 8 + (lane & 3) * 2;
                if (col > qi0)     sacc[ni][0] = NEGINF;
                if (col + 1 > qi0) sacc[ni][1] = NEGINF;
                if (col > qi0 + 8)     sacc[ni][2] = NEGINF;
                if (col + 1 > qi0 + 8) sacc[ni][3] = NEGINF;
            }
        }

        // ---- online softmax ----
        float mx0 = NEGINF, mx1 = NEGINF;
#pragma unroll
        for (int ni = 0; ni < 8; ni++) {
            mx0 = fmaxf(mx0, fmaxf(sacc[ni][0], sacc[ni][1]));
            mx1 = fmaxf(mx1, fmaxf(sacc[ni][2], sacc[ni][3]));
        }
        mx0 = fmaxf(mx0, __shfl_xor_sync(0xffffffffu, mx0, 1));
        mx0 = fmaxf(mx0, __shfl_xor_sync(0xffffffffu, mx0, 2));
        mx1 = fmaxf(mx1, __shfl_xor_sync(0xffffffffu, mx1, 1));
        mx1 = fmaxf(mx1, __shfl_xor_sync(0xffffffffu, mx1, 2));

        const float nm0 = fmaxf(m0, mx0), nm1 = fmaxf(m1, mx1);
        const float cr0 = __expf(m0 - nm0), cr1 = __expf(m1 - nm1);
        m0 = nm0; m1 = nm1;

        float s0 = 0.f, s1 = 0.f;
#pragma unroll
        for (int ni = 0; ni < 8; ni++) {
            sacc[ni][0] = __expf(sacc[ni][0] - nm0);
            sacc[ni][1] = __expf(sacc[ni][1] - nm0);
            sacc[ni][2] = __expf(sacc[ni][2] - nm1);
            sacc[ni][3] = __expf(sacc[ni][3] - nm1);
            s0 += sacc[ni][0] + sacc[ni][1];
            s1 += sacc[ni][2] + sacc[ni][3];
        }
        s0 += __shfl_xor_sync(0xffffffffu, s0, 1);
        s0 += __shfl_xor_sync(0xffffffffu, s0, 2);
        s1 += __shfl_xor_sync(0xffffffffu, s1, 1);
        s1 += __shfl_xor_sync(0xffffffffu, s1, 2);
        l0 = l0 * cr0 + s0;
        l1 = l1 * cr1 + s1;

#pragma unroll
        for (int ni = 0; ni < 8; ni++) {
            oacc[ni][0] *= cr0; oacc[ni][1] *= cr0;
            oacc[ni][2] *= cr1; oacc[ni][3] *= cr1;
        }

        // ---- O += P V ----
#pragma unroll
        for (int kk = 0; kk < 4; kk++) {
            u32 ph[4];
            ph[0] = pack_h2(sacc[2 * kk][0],     sacc[2 * kk][1]);
            ph[1] = pack_h2(sacc[2 * kk][2],     sacc[2 * kk][3]);
            ph[2] = pack_h2(sacc[2 * kk + 1][0], sacc[2 * kk + 1][1]);
            ph[3] = pack_h2(sacc[2 * kk + 1][2], sacc[2 * kk + 1][3]);
#pragma unroll
            for (int nj = 0; nj < 4; nj++) {
                u32 fv[4];
                u32 off = (u32)(kk * 16 + (lane & 15)) * 128 + (u32)nj * 32 + (u32)((lane >> 4) << 4);
                off ^= (off >> 3) & 0x70;
                LDX4T(fv, stg + 8192 + off);
                MMA16816H(oacc[nj * 2 + 0], ph, fv[0], fv[1]);
                MMA16816H(oacc[nj * 2 + 1], ph, fv[2], fv[3]);
            }
        }
        __syncthreads();
    }

    // ---- epilogue: normalize, write single fp16 to g_a16 ----
    const float inv0 = 1.f / l0, inv1 = 1.f / l1;
    const size_t r0off = ((size_t)b * Sc + qi0) * Dc + h * HDc;
    const size_t r1off = ((size_t)b * Sc + qi0 + 8) * Dc + h * HDc;
#pragma unroll
    for (int ni = 0; ni < 8; ni++) {
        const int col = ni * 8 + (lane & 3) * 2;
        *reinterpret_cast<u32*>(g_a16 + r0off + col) = pack_h2(oacc[ni][0] * inv0, oacc[ni][1] * inv0);
        *reinterpret_cast<u32*>(g_a16 + r1off + col) = pack_h2(oacc[ni][2] * inv1, oacc[ni][3] * inv1);
    }
}

// ---------------------------------------------------------------------------
extern "C" void kernel_launch(void* const* d_in, const int* in_sizes, int n_in,
                              void* d_out, int out_size)
{
    const float* X     = (const float*)d_in[0];
    const float* W_qkv = (const float*)d_in[1];
    const float* b_qkv = (const float*)d_in[2];
    const float* W_out = (const float*)d_in[3];
    const float* b_out = (const float*)d_in[4];
    float* out = (float*)d_out;

    cudaFuncSetAttribute(gemm_mma<0>, cudaFuncAttributeMaxDynamicSharedMemorySize, GEMM_SMEM);
    cudaFuncSetAttribute(gemm_mma<1>, cudaFuncAttributeMaxDynamicSharedMemorySize, GEMM_SMEM);
    cudaFuncSetAttribute(attn_mma, cudaFuncAttributeMaxDynamicSharedMemorySize, ATT_SMEM);

    // fp16 conversions
    split_x<<<1024, 256>>>(X, Mtot * Dc / 4);
    split_tr<0><<<dim3(3 * Dc / 32, Dc / 32), dim3(32, 8)>>>(W_qkv, Dc, 3 * Dc);
    split_tr<1><<<dim3(Dc / 32, Dc / 32), dim3(32, 8)>>>(W_out, Dc, Dc);

    // 1) QKV projection (single-product fp16, 128x128 tile) -> Q(scaled)/K/V fp16
    gemm_mma<0><<<dim3(3 * Dc / 128, Mtot / 128), 256, GEMM_SMEM>>>(b_qkv, nullptr, 3 * Dc, Dc);

    // 2) causal flash attention -> g_a16 (fp16, [b,s,D])
    attn_mma<<<dim3(Sc / 128, Bc * Hc), 256, ATT_SMEM>>>();

    // 3) out-proj (single-product fp16, 128x128 tile) -> d_out
    gemm_mma<1><<<dim3(Dc / 128, Mtot / 128), 256, GEMM_SMEM>>>(b_out, out, Dc, Dc);
}